// round 14
// baseline (speedup 1.0000x reference)
#include <cuda_runtime.h>
#include <cuda_bf16.h>
#include <math.h>

#define NN     50000
#define NEDGE  600000
#define HDIM   128
#define NPASS  5
#define LN_EPS 1e-6f

#define NT128      ((NN + 127) / 128)    // 391  (mma tiles, nodes)
#define ET128      ((NEDGE + 127) / 128) // 4688 (mma tiles, edges)

typedef unsigned int uint32;
typedef unsigned short ushort16;

// Persistent device scratch — double-buffered node features
__device__ float g_n0[NN * HDIM];
__device__ float g_n1[NN * HDIM];
__device__ float g_hsum[NN * HDIM];
__device__ float g_cagg[NN * HDIM];
__device__ float g_T1[HDIM * HDIM];     // W1e @ Wm_bot
__device__ float g_tvec[HDIM];          // b1e @ Wm_bot
__device__ float g_bg[HDIM];

// Receiver-CSR of the edge list (built once per launch)
__device__ int g_rowptr[NN + 1];
__device__ int g_cursor[NN];
__device__ int g_col[NEDGE];

// Split-bf16 weight tables, [N][K] k-contiguous (transposed)
__device__ __align__(16) ushort16 g_BtopH[HDIM * HDIM], g_BtopL[HDIM * HDIM]; // W0_top
__device__ __align__(16) ushort16 g_BWfH [HDIM * HDIM], g_BWfL [HDIM * HDIM]; // Wm_top@W0_bot
__device__ __align__(16) ushort16 g_BresH[HDIM * HDIM], g_BresL[HDIM * HDIM]; // Wn
__device__ __align__(16) ushort16 g_BoutH[HDIM * HDIM], g_BoutL[HDIM * HDIM]; // W1
__device__ __align__(16) ushort16 g_Ben1H[HDIM * HDIM], g_Ben1L[HDIM * HDIM]; // enc W1
__device__ __align__(16) ushort16 g_BWgH[HDIM * HDIM],  g_BWgL[HDIM * HDIM];  // (W1e@Wm_bot)@W0_bot
__device__ __align__(16) ushort16 g_BdecH[HDIM * HDIM], g_BdecL[HDIM * HDIM]; // dec W0
__device__ __align__(16) ushort16 g_BeH[HDIM * 16],   g_BeL[HDIM * 16];       // edge W0 [n][16k]
__device__ __align__(16) ushort16 g_Ben0H[HDIM * 32], g_Ben0L[HDIM * 32];     // enc W0 [n][32k]

// ---------------------------------------------------------------------------
// bf16 helpers + MMA
// ---------------------------------------------------------------------------
__device__ __forceinline__ uint32 pack_bf2(float x, float y) {
    __nv_bfloat162 t = __floats2bfloat162_rn(x, y);
    return *reinterpret_cast<uint32*>(&t);
}
__device__ __forceinline__ void split_bf(float v, ushort16& h, ushort16& l) {
    __nv_bfloat16 hb = __float2bfloat16_rn(v);
    float lo = v - __bfloat162float(hb);
    __nv_bfloat16 lb = __float2bfloat16_rn(lo);
    h = *reinterpret_cast<ushort16*>(&hb);
    l = *reinterpret_cast<ushort16*>(&lb);
}
__device__ __forceinline__ void split_pack2(float2 v, uint32& h, uint32& l) {
    float ex = __bfloat162float(__float2bfloat16_rn(v.x));
    float ey = __bfloat162float(__float2bfloat16_rn(v.y));
    h = pack_bf2(v.x, v.y);
    l = pack_bf2(v.x - ex, v.y - ey);
}
#define MMA16816(d, a0,a1,a2,a3, b0,b1) \
    asm volatile("mma.sync.aligned.m16n8k16.row.col.f32.bf16.bf16.f32 " \
        "{%0,%1,%2,%3},{%4,%5,%6,%7},{%8,%9},{%0,%1,%2,%3};" \
        : "+f"((d)[0]), "+f"((d)[1]), "+f"((d)[2]), "+f"((d)[3]) \
        : "r"(a0), "r"(a1), "r"(a2), "r"(a3), "r"(b0), "r"(b1))

// ---------------------------------------------------------------------------
// Weight folds
// ---------------------------------------------------------------------------
__global__ void k_fold1(const float* __restrict__ W1e, const float* __restrict__ b1e,
                        const float* __restrict__ Wm) {
    __shared__ float a[HDIM];
    int j = threadIdx.x;
    a[j] = (blockIdx.x < 128) ? W1e[blockIdx.x * HDIM + j] : b1e[j];
    __syncthreads();
    float s = 0.f;
#pragma unroll 8
    for (int l = 0; l < HDIM; l++)
        s = fmaf(a[l], Wm[(HDIM + l) * HDIM + j], s);
    if (blockIdx.x < 128) g_T1[blockIdx.x * HDIM + j] = s;
    else                  g_tvec[j] = s;
}

// bid<128: Wg row bid (split to g_BWg); bid==128: bg; bid>=129: Wf row (split)
__global__ void k_fold2(const float* __restrict__ W0n, const float* __restrict__ Wm) {
    __shared__ float a[HDIM];
    int j = threadIdx.x;
    int bid = blockIdx.x;
    if (bid < 128)       a[j] = g_T1[bid * HDIM + j];
    else if (bid == 128) a[j] = g_tvec[j];
    else                 a[j] = Wm[(bid - 129) * HDIM + j];
    __syncthreads();
    float s = 0.f;
#pragma unroll 8
    for (int l = 0; l < HDIM; l++)
        s = fmaf(a[l], W0n[(HDIM + l) * HDIM + j], s);
    if (bid < 128) {
        ushort16 h, l2; split_bf(s, h, l2);
        g_BWgH[j * HDIM + bid] = h;      // [n][k], k = bid
        g_BWgL[j * HDIM + bid] = l2;
    } else if (bid == 128) g_bg[j] = s;
    else {
        int k = bid - 129;
        ushort16 h, l2; split_bf(s, h, l2);
        g_BWfH[j * HDIM + k] = h;
        g_BWfL[j * HDIM + k] = l2;
    }
}

// Merged split of five [128][128] weights; dest picked in device code.
__global__ void k_splitB(const float* __restrict__ W0, const float* __restrict__ Wn,
                         const float* __restrict__ W1, const float* __restrict__ We1,
                         const float* __restrict__ Wd0) {
    int which = blockIdx.x >> 6;
    const float* W; ushort16* dH; ushort16* dL;
    if (which == 0)      { W = W0;  dH = g_BtopH; dL = g_BtopL; }
    else if (which == 1) { W = Wn;  dH = g_BresH; dL = g_BresL; }
    else if (which == 2) { W = W1;  dH = g_BoutH; dL = g_BoutL; }
    else if (which == 3) { W = We1; dH = g_Ben1H; dL = g_Ben1L; }
    else                 { W = Wd0; dH = g_BdecH; dL = g_BdecL; }
    int idx = (blockIdx.x & 63) * 256 + threadIdx.x;
    int k = idx >> 7, n = idx & 127;
    ushort16 h, l;
    split_bf(W[k * HDIM + n], h, l);
    dH[n * HDIM + k] = h;
    dL[n * HDIM + k] = l;
}

// Split + transpose small weights: edge W0 [16][128], enc W0 [32][128]
__global__ void k_splitE(const float* __restrict__ W0e, const float* __restrict__ W0n) {
    int idx = blockIdx.x * 256 + threadIdx.x;   // 2048 + 4096
    if (idx < 2048) {
        int n = idx & 127, k = idx >> 7;
        ushort16 h, l;
        split_bf(W0e[k * HDIM + n], h, l);
        g_BeH[n * 16 + k] = h;
        g_BeL[n * 16 + k] = l;
    } else if (idx < 6144) {
        int i = idx - 2048;
        int n = i & 127, k = i >> 7;
        ushort16 h, l;
        split_bf(W0n[k * HDIM + n], h, l);
        g_Ben0H[n * 32 + k] = h;
        g_Ben0L[n * 32 + k] = l;
    }
}

// ---------------------------------------------------------------------------
// CSR build + zero helpers
// ---------------------------------------------------------------------------
__global__ void k_zero_pre() {
    int i = blockIdx.x * blockDim.x + threadIdx.x;
    if (i < NN * 32) ((float4*)g_hsum)[i] = make_float4(0.f, 0.f, 0.f, 0.f);
    else {
        int d = i - NN * 32;
        if (d < NN / 4) ((int4*)g_cursor)[d] = make_int4(0, 0, 0, 0);
    }
}

__global__ void k_hist(const int* __restrict__ recvs) {
    int e = blockIdx.x * 256 + threadIdx.x;
    if (e < NEDGE) atomicAdd(g_cursor + recvs[e], 1);
}

__global__ void __launch_bounds__(1024) k_scan() {
    __shared__ int partial[1024];
    const int CHUNK = (NN + 1023) / 1024;
    int t = threadIdx.x;
    int beg = t * CHUNK, end = min(beg + CHUNK, NN);
    int s = 0;
    for (int i = beg; i < end; i++) s += g_cursor[i];
    partial[t] = s;
    __syncthreads();
    for (int off = 1; off < 1024; off <<= 1) {
        int v = (t >= off) ? partial[t - off] : 0;
        __syncthreads();
        partial[t] += v;
        __syncthreads();
    }
    int base = (t > 0) ? partial[t - 1] : 0;
    for (int i = beg; i < end; i++) {
        int c = g_cursor[i];
        g_rowptr[i] = base;
        g_cursor[i] = base;
        base += c;
    }
    if (t == 1023) g_rowptr[NN] = partial[1023];
}

__global__ void k_fillcsr(const int* __restrict__ senders,
                          const int* __restrict__ recvs) {
    int e = blockIdx.x * 256 + threadIdx.x;
    if (e < NEDGE) {
        int pos = atomicAdd(g_cursor + recvs[e], 1);
        g_col[pos] = senders[e];
    }
}

// ===========================================================================
// Shared MMA building blocks
// ===========================================================================
#define BST 20

__device__ __forceinline__ void fillB_g(uint32* BhU, uint32* BlU,
                                        const ushort16* __restrict__ gH,
                                        const ushort16* __restrict__ gL,
                                        int koff, int tid) {
    const uint4* sH = (const uint4*)gH;
    const uint4* sL = (const uint4*)gL;
    int kq0 = koff >> 3;
#pragma unroll
    for (int i = 0; i < 2; i++) {
        int p = tid + i * 256;
        int n = p >> 2, kq = p & 3;
        *(uint4*)(BhU + n * BST + 4 * kq) = sH[n * 16 + kq0 + kq];
        *(uint4*)(BlU + n * BST + 4 * kq) = sL[n * 16 + kq0 + kq];
    }
}

__device__ __forceinline__ void fillA(uint32* AhU, uint32* AlU,
                                      const float* __restrict__ src,
                                      int row0, int koff, int tid) {
#pragma unroll
    for (int i = 0; i < 4; i++) {
        int p = tid + i * 256;
        int row = p >> 3, q = p & 7;
        int gr = row0 + row;
        float4 v = make_float4(0.f, 0.f, 0.f, 0.f);
        if (gr < NN) v = *(const float4*)(src + (long)gr * HDIM + koff + 4 * q);
        float ex = __bfloat162float(__float2bfloat16_rn(v.x));
        float ey = __bfloat162float(__float2bfloat16_rn(v.y));
        float ez = __bfloat162float(__float2bfloat16_rn(v.z));
        float ew = __bfloat162float(__float2bfloat16_rn(v.w));
        uint2 hh = make_uint2(pack_bf2(v.x, v.y), pack_bf2(v.z, v.w));
        uint2 ll = make_uint2(pack_bf2(v.x - ex, v.y - ey), pack_bf2(v.z - ez, v.w - ew));
        *(uint2*)(AhU + row * BST + 2 * q) = hh;
        *(uint2*)(AlU + row * BST + 2 * q) = ll;
    }
}

template<int AS>
__device__ __forceinline__ void mma_chunk(const uint32* AhU, const uint32* AlU,
                                          const uint32* BhU, const uint32* BlU,
                                          float acc[16][4], int rw0, int gid, int tg) {
#pragma unroll
    for (int kb2 = 0; kb2 <= 8; kb2 += 8) {
        int a0i = (rw0 + gid) * AS + kb2 + tg;
        int a1i = a0i + 8 * AS;
        uint32 ah0 = AhU[a0i],     ah1 = AhU[a1i];
        uint32 ah2 = AhU[a0i + 4], ah3 = AhU[a1i + 4];
        uint32 al0 = AlU[a0i],     al1 = AlU[a1i];
        uint32 al2 = AlU[a0i + 4], al3 = AlU[a1i + 4];
#pragma unroll
        for (int t = 0; t < 16; t++) {
            int bi = (8 * t + gid) * BST + kb2 + tg;
            uint32 bh0 = BhU[bi], bh1 = BhU[bi + 4];
            uint32 bl0 = BlU[bi], bl1 = BlU[bi + 4];
            MMA16816(acc[t], ah0, ah1, ah2, ah3, bh0, bh1);
            MMA16816(acc[t], ah0, ah1, ah2, ah3, bl0, bl1);
            MMA16816(acc[t], al0, al1, al2, al3, bh0, bh1);
        }
    }
}

// ===========================================================================
// MMA node encoder: n0 = relu(x@W0+b0)@W1+b1 (fp32 output only)
// ===========================================================================
#define E_BH 0
#define E_BL (E_BH + 128 * BST)
#define E_HH (E_BL + 128 * BST)
#define E_HL (E_HH + 128 * 68)
#define SM_ENC2 ((E_HL + 128 * 68) * 4)    // 90112 B

__global__ void __launch_bounds__(256, 2) k_node_enc_mma(
        const float* __restrict__ x,
        const float* __restrict__ b0, const float* __restrict__ b1) {
    extern __shared__ uint32 smu[];
    uint32* BhU = smu + E_BH;
    uint32* BlU = smu + E_BL;
    uint32* HhU = smu + E_HH;
    uint32* HlU = smu + E_HL;

    const int tid = threadIdx.x;
    const int w = tid >> 5, lane = tid & 31;
    const int gid = lane >> 2, tg = lane & 3;
    const int rw0 = w * 16;
    const int row0 = blockIdx.x * 128;
    const int r_e = row0 + rw0 + gid;
    const int r_o = r_e + 8;

    // layer-1 B table (dense [n][16 u32])
#pragma unroll
    for (int i = 0; i < 2; i++) {
        int p = tid + i * 256;   // 512 uint4
        *(uint4*)(BhU + 4 * p) = ((const uint4*)g_Ben0H)[p];
        *(uint4*)(BlU + 4 * p) = ((const uint4*)g_Ben0L)[p];
    }

    // A fragments direct from gmem (K=32): 2 k-blocks
    float2 z = make_float2(0.f, 0.f);
    uint32 ah[2][4], al[2][4];
#pragma unroll
    for (int kb = 0; kb < 2; kb++) {
        float2 vE0 = (r_e < NN) ? *(const float2*)(x + (long)r_e * 32 + kb * 16 + 2 * tg)     : z;
        float2 vO0 = (r_o < NN) ? *(const float2*)(x + (long)r_o * 32 + kb * 16 + 2 * tg)     : z;
        float2 vE1 = (r_e < NN) ? *(const float2*)(x + (long)r_e * 32 + kb * 16 + 8 + 2 * tg) : z;
        float2 vO1 = (r_o < NN) ? *(const float2*)(x + (long)r_o * 32 + kb * 16 + 8 + 2 * tg) : z;
        split_pack2(vE0, ah[kb][0], al[kb][0]);
        split_pack2(vO0, ah[kb][1], al[kb][1]);
        split_pack2(vE1, ah[kb][2], al[kb][2]);
        split_pack2(vO1, ah[kb][3], al[kb][3]);
    }
    __syncthreads();

    float acc[16][4];
#pragma unroll
    for (int t = 0; t < 16; t++) {
        int col = 8 * t + 2 * tg;
        float2 bb = *(const float2*)(b0 + col);
        acc[t][0] = bb.x; acc[t][1] = bb.y;
        acc[t][2] = bb.x; acc[t][3] = bb.y;
    }
#pragma unroll
    for (int kb = 0; kb < 2; kb++) {
#pragma unroll
        for (int t = 0; t < 16; t++) {
            int bi = (8 * t + gid) * 16 + kb * 8 + tg;
            uint32 bh0 = BhU[bi], bh1 = BhU[bi + 4];
            uint32 bl0 = BlU[bi], bl1 = BlU[bi + 4];
            MMA16816(acc[t], ah[kb][0], ah[kb][1], ah[kb][2], ah[kb][3], bh0, bh1);
            MMA16816(acc[t], ah[kb][0], ah[kb][1], ah[kb][2], ah[kb][3], bl0, bl1);
            MMA16816(acc[t], al[kb][0], al[kb][1], al[kb][2], al[kb][3], bh0, bh1);
        }
    }

    // relu + split-store h
#pragma unroll
    for (int t = 0; t < 16; t++) {
        float h0 = fmaxf(acc[t][0], 0.f), h1 = fmaxf(acc[t][1], 0.f);
        float h2 = fmaxf(acc[t][2], 0.f), h3 = fmaxf(acc[t][3], 0.f);
        int ie = (rw0 + gid) * 68 + 4 * t + tg;
        int io = ie + 8 * 68;
        uint32 hh, ll;
        split_pack2(make_float2(h0, h1), hh, ll);
        HhU[ie] = hh; HlU[ie] = ll;
        split_pack2(make_float2(h2, h3), hh, ll);
        HhU[io] = hh; HlU[io] = ll;
    }

    // layer 2: K = 128 over h
#pragma unroll
    for (int t = 0; t < 16; t++) {
        int col = 8 * t + 2 * tg;
        float2 bb = *(const float2*)(b1 + col);
        acc[t][0] = bb.x; acc[t][1] = bb.y;
        acc[t][2] = bb.x; acc[t][3] = bb.y;
    }
    for (int c = 0; c < 4; c++) {
        __syncthreads();
        fillB_g(BhU, BlU, g_Ben1H, g_Ben1L, c * 32, tid);
        __syncthreads();
        mma_chunk<68>(HhU + 16 * c, HlU + 16 * c, BhU, BlU, acc, rw0, gid, tg);
    }

    // write fp32 n0
#pragma unroll
    for (int t = 0; t < 16; t++) {
        int col = 8 * t + 2 * tg;
        if (r_e < NN)
            *(float2*)(g_n0 + (long)r_e * HDIM + col) = make_float2(acc[t][0], acc[t][1]);
        if (r_o < NN)
            *(float2*)(g_n0 + (long)r_o * HDIM + col) = make_float2(acc[t][2], acc[t][3]);
    }
}

// ===========================================================================
// MMA edge encoder + scatter: h = relu(x@W0e+b0e); g_hsum[recv] += h
// ===========================================================================
#define SM_EDGE ((1024 + 1024 + 128 * 132) * 4)   // 75776 B

__global__ void __launch_bounds__(256, 2) k_edge_mma(
        const float* __restrict__ x, const float* __restrict__ b0e,
        const int* __restrict__ recvs) {
    extern __shared__ uint32 smu[];
    uint32* BhU  = smu;
    uint32* BlU  = smu + 1024;
    float*  Hout = (float*)(smu + 2048);

    const int tid = threadIdx.x;
    const int w = tid >> 5, lane = tid & 31;
    const int gid = lane >> 2, tg = lane & 3;
    const int rw0 = w * 16;
    const int row0 = blockIdx.x * 128;
    const int eE = row0 + rw0 + gid;
    const int eO = eE + 8;

#pragma unroll
    for (int i = 0; i < 4; i++) {
        int p = tid + i * 256;
        BhU[p] = ((const uint32*)g_BeH)[p];
        BlU[p] = ((const uint32*)g_BeL)[p];
    }

    float2 z = make_float2(0.f, 0.f);
    float2 vE0 = (eE < NEDGE) ? *(const float2*)(x + (long)eE * 16 + 2 * tg)     : z;
    float2 vE1 = (eE < NEDGE) ? *(const float2*)(x + (long)eE * 16 + 8 + 2 * tg) : z;
    float2 vO0 = (eO < NEDGE) ? *(const float2*)(x + (long)eO * 16 + 2 * tg)     : z;
    float2 vO1 = (eO < NEDGE) ? *(const float2*)(x + (long)eO * 16 + 8 + 2 * tg) : z;
    uint32 ah0, al0, ah1, al1, ah2, al2, ah3, al3;
    split_pack2(vE0, ah0, al0);
    split_pack2(vO0, ah1, al1);
    split_pack2(vE1, ah2, al2);
    split_pack2(vO1, ah3, al3);
    __syncthreads();

    float acc[16][4];
#pragma unroll
    for (int t = 0; t < 16; t++) {
        int col = 8 * t + 2 * tg;
        float2 bb = *(const float2*)(b0e + col);
        acc[t][0] = bb.x; acc[t][1] = bb.y;
        acc[t][2] = bb.x; acc[t][3] = bb.y;
    }
#pragma unroll
    for (int t = 0; t < 16; t++) {
        int bi = (8 * t + gid) * 8 + tg;
        uint32 bh0 = BhU[bi], bh1 = BhU[bi + 4];
        uint32 bl0 = BlU[bi], bl1 = BlU[bi + 4];
        MMA16816(acc[t], ah0, ah1, ah2, ah3, bh0, bh1);
        MMA16816(acc[t], ah0, ah1, ah2, ah3, bl0, bl1);
        MMA16816(acc[t], al0, al1, al2, al3, bh0, bh1);
    }

#pragma unroll
    for (int t = 0; t < 16; t++) {
        int col = 8 * t + 2 * tg;
        *(float2*)(Hout + (rw0 + gid)     * 132 + col) =
            make_float2(fmaxf(acc[t][0], 0.f), fmaxf(acc[t][1], 0.f));
        *(float2*)(Hout + (rw0 + gid + 8) * 132 + col) =
            make_float2(fmaxf(acc[t][2], 0.f), fmaxf(acc[t][3], 0.f));
    }
    __syncthreads();

    int j = lane * 4;
    for (int r = 0; r < 16; r++) {
        int e = row0 + rw0 + r;
        if (e < NEDGE) {
            int rv = __ldg(recvs + e);
            float4 v = *(const float4*)(Hout + (rw0 + r) * 132 + j);
            float* dst = g_hsum + (long)rv * HDIM + j;
            asm volatile("red.global.add.v4.f32 [%0], {%1, %2, %3, %4};"
                         :: "l"(dst), "f"(v.x), "f"(v.y), "f"(v.z), "f"(v.w) : "memory");
        }
    }
}

// ===========================================================================
// MMA cagg: c_agg = g_hsum @ Wg + deg * bg
// ===========================================================================
#define SM_CAG (4 * 128 * BST * 4)     // 40960 B

__global__ void __launch_bounds__(256, 2) k_cagg_mma() {
    extern __shared__ uint32 smu[];
    uint32* AhU = smu;
    uint32* AlU = smu + 128 * BST;
    uint32* BhU = smu + 2 * 128 * BST;
    uint32* BlU = smu + 3 * 128 * BST;

    const int tid = threadIdx.x;
    const int w = tid >> 5, lane = tid & 31;
    const int gid = lane >> 2, tg = lane & 3;
    const int rw0 = w * 16;
    const int row0 = blockIdx.x * 128;
    const int r_e = row0 + rw0 + gid;
    const int r_o = r_e + 8;

    float acc[16][4];
    {
        float de = (r_e < NN) ? (float)(g_rowptr[r_e + 1] - g_rowptr[r_e]) : 0.f;
        float dd = (r_o < NN) ? (float)(g_rowptr[r_o + 1] - g_rowptr[r_o]) : 0.f;
#pragma unroll
        for (int t = 0; t < 16; t++) {
            int col = 8 * t + 2 * tg;
            float2 bb = *(const float2*)(g_bg + col);
            acc[t][0] = de * bb.x; acc[t][1] = de * bb.y;
            acc[t][2] = dd * bb.x; acc[t][3] = dd * bb.y;
        }
    }
    for (int c = 0; c < 4; c++) {
        __syncthreads();
        fillA(AhU, AlU, g_hsum, row0, c * 32, tid);
        fillB_g(BhU, BlU, g_BWgH, g_BWgL, c * 32, tid);
        __syncthreads();
        mma_chunk<BST>(AhU, AlU, BhU, BlU, acc, rw0, gid, tg);
    }
#pragma unroll
    for (int t = 0; t < 16; t++) {
        int col = 8 * t + 2 * tg;
        if (r_e < NN)
            *(float2*)(g_cagg + (long)r_e * HDIM + col) = make_float2(acc[t][0], acc[t][1]);
        if (r_o < NN)
            *(float2*)(g_cagg + (long)r_o * HDIM + col) = make_float2(acc[t][2], acc[t][3]);
    }
}

// ===========================================================================
// Fused MMA node update (CSR gather, dual-row 8-edge chunks = MLP16)
// ===========================================================================
#define U_AH 0
#define U_AL (U_AH + 128 * BST)
#define U_BH (U_AL + 128 * BST)
#define U_BL (U_BH + 128 * BST)
#define U_HH (U_BL + 128 * BST)
#define U_HL (U_HH + 128 * 68)
#define U_END (U_HL + 128 * 68)
#define SM_MMA (U_END * 4)          // 110592 bytes

__global__ void __launch_bounds__(256, 2) k_node_upd_mma(
        const float* __restrict__ b0, const float* __restrict__ b1,
        const float* __restrict__ lng, const float* __restrict__ lnb,
        int par) {
    extern __shared__ uint32 smu[];
    uint32* AhU = smu + U_AH;
    uint32* AlU = smu + U_AL;
    uint32* BhU = smu + U_BH;
    uint32* BlU = smu + U_BL;
    uint32* HhU = smu + U_HH;
    uint32* HlU = smu + U_HL;

    const float* ncur = (par == 0) ? g_n0 : g_n1;
    float*       nnxt = (par == 0) ? g_n1 : g_n0;

    const int tid = threadIdx.x;
    const int w = tid >> 5, lane = tid & 31;
    const int gid = lane >> 2, tg = lane & 3;
    const int rw0 = w * 16;
    const int row0 = blockIdx.x * 128;
    const int r_e = row0 + rw0 + gid;
    const int r_o = r_e + 8;
    const int jj = lane * 4;

    // ---- CSR gather, dual-row with 8-edge chunks (16 loads in flight) ----
    for (int rr = 0; rr < 8; rr++) {
        int rowA = rw0 + rr, rowB = rowA + 8;
        int grA = row0 + rowA, grB = row0 + rowB;
        float A0 = 0.f, A1 = 0.f, A2 = 0.f, A3 = 0.f;
        float B0 = 0.f, B1 = 0.f, B2 = 0.f, B3 = 0.f;
        int eA = 0, nA = 0, eB = 0, nB = 0;
        if (grA < NN) { eA = g_rowptr[grA]; nA = g_rowptr[grA + 1]; }
        if (grB < NN) { eB = g_rowptr[grB]; nB = g_rowptr[grB + 1]; }
        // main: both rows take 8 edges at once
        while (eA + 8 <= nA && eB + 8 <= nB) {
            float4 u[8], v[8];
#pragma unroll
            for (int q = 0; q < 8; q++) {
                int sa = g_col[eA + q];
                int sb = g_col[eB + q];
                u[q] = *(const float4*)(ncur + (long)sa * HDIM + jj);
                v[q] = *(const float4*)(ncur + (long)sb * HDIM + jj);
            }
#pragma unroll
            for (int q = 0; q < 8; q++) {
                A0 += u[q].x; A1 += u[q].y; A2 += u[q].z; A3 += u[q].w;
                B0 += v[q].x; B1 += v[q].y; B2 += v[q].z; B3 += v[q].w;
            }
            eA += 8; eB += 8;
        }
        // tails: 4-chunks then scalar, per row
        for (; eA + 4 <= nA; eA += 4) {
            int a0 = g_col[eA], a1 = g_col[eA+1], a2 = g_col[eA+2], a3 = g_col[eA+3];
            float4 u0 = *(const float4*)(ncur + (long)a0 * HDIM + jj);
            float4 u1 = *(const float4*)(ncur + (long)a1 * HDIM + jj);
            float4 u2 = *(const float4*)(ncur + (long)a2 * HDIM + jj);
            float4 u3 = *(const float4*)(ncur + (long)a3 * HDIM + jj);
            A0 += u0.x + u1.x + u2.x + u3.x;
            A1 += u0.y + u1.y + u2.y + u3.y;
            A2 += u0.z + u1.z + u2.z + u3.z;
            A3 += u0.w + u1.w + u2.w + u3.w;
        }
        for (; eA < nA; eA++) {
            int s = g_col[eA];
            float4 uv = *(const float4*)(ncur + (long)s * HDIM + jj);
            A0 += uv.x; A1 += uv.y; A2 += uv.z; A3 += uv.w;
        }
        for (; eB + 4 <= nB; eB += 4) {
            int b0i = g_col[eB], b1i = g_col[eB+1], b2i = g_col[eB+2], b3i = g_col[eB+3];
            float4 w0 = *(const float4*)(ncur + (long)b0i * HDIM + jj);
            float4 w1 = *(const float4*)(ncur + (long)b1i * HDIM + jj);
            float4 w2 = *(const float4*)(ncur + (long)b2i * HDIM + jj);
            float4 w3 = *(const float4*)(ncur + (long)b3i * HDIM + jj);
            B0 += w0.x + w1.x + w2.x + w3.x;
            B1 += w0.y + w1.y + w2.y + w3.y;
            B2 += w0.z + w1.z + w2.z + w3.z;
            B3 += w0.w + w1.w + w2.w + w3.w;
        }
        for (; eB < nB; eB++) {
            int s = g_col[eB];
            float4 uv = *(const float4*)(ncur + (long)s * HDIM + jj);
            B0 += uv.x; B1 += uv.y; B2 += uv.z; B3 += uv.w;
        }
        uint32 h0, l0, h1, l1;
        split_pack2(make_float2(A0, A1), h0, l0);
        split_pack2(make_float2(A2, A3), h1, l1);
        *(uint2*)(HhU + rowA * 68 + lane * 2) = make_uint2(h0, h1);
        *(uint2*)(HlU + rowA * 68 + lane * 2) = make_uint2(l0, l1);
        split_pack2(make_float2(B0, B1), h0, l0);
        split_pack2(make_float2(B2, B3), h1, l1);
        *(uint2*)(HhU + rowB * 68 + lane * 2) = make_uint2(h0, h1);
        *(uint2*)(HlU + rowB * 68 + lane * 2) = make_uint2(l0, l1);
    }

    float acc[16][4];

    // ---- hidden accumulator init: b0 + c_agg ----
#pragma unroll
    for (int t = 0; t < 16; t++) {
        int col = 8 * t + 2 * tg;
        float2 bb = *(const float2*)(b0 + col);
        float2 ce = (r_e < NN) ? *(const float2*)(g_cagg + (long)r_e * HDIM + col)
                               : make_float2(0.f, 0.f);
        float2 co = (r_o < NN) ? *(const float2*)(g_cagg + (long)r_o * HDIM + col)
                               : make_float2(0.f, 0.f);
        acc[t][0] = bb.x + ce.x; acc[t][1] = bb.y + ce.y;
        acc[t][2] = bb.x + co.x; acc[t][3] = bb.y + co.y;
    }

    // ---- hidden: K = 256 — n chunks from gmem, S chunks from H ----
    for (int c = 0; c < 8; c++) {
        int koff = (c & 3) * 32;
        __syncthreads();
        if (c < 4) fillA(AhU, AlU, ncur, row0, koff, tid);
        fillB_g(BhU, BlU, (c < 4) ? g_BtopH : g_BWfH,
                          (c < 4) ? g_BtopL : g_BWfL, koff, tid);
        __syncthreads();
        if (c < 4) mma_chunk<BST>(AhU, AlU, BhU, BlU, acc, rw0, gid, tg);
        else       mma_chunk<68>(HhU + 16 * (c - 4), HlU + 16 * (c - 4),
                                 BhU, BlU, acc, rw0, gid, tg);
    }

    // ---- relu + split-store h to smem H ----
    __syncthreads();
#pragma unroll
    for (int t = 0; t < 16; t++) {
        float h0 = fmaxf(acc[t][0], 0.f), h1 = fmaxf(acc[t][1], 0.f);
        float h2 = fmaxf(acc[t][2], 0.f), h3 = fmaxf(acc[t][3], 0.f);
        int ie = (rw0 + gid) * 68 + 4 * t + tg;
        int io = ie + 8 * 68;
        uint32 hh, ll;
        split_pack2(make_float2(h0, h1), hh, ll);
        HhU[ie] = hh; HlU[ie] = ll;
        split_pack2(make_float2(h2, h3), hh, ll);
        HhU[io] = hh; HlU[io] = ll;
    }

    // ---- residual: acc = n @ Wn ----
#pragma unroll
    for (int t = 0; t < 16; t++) {
        acc[t][0] = 0.f; acc[t][1] = 0.f; acc[t][2] = 0.f; acc[t][3] = 0.f;
    }
    for (int c = 0; c < 4; c++) {
        __syncthreads();
        fillA(AhU, AlU, ncur, row0, c * 32, tid);
        fillB_g(BhU, BlU, g_BresH, g_BresL, c * 32, tid);
        __syncthreads();
        mma_chunk<BST>(AhU, AlU, BhU, BlU, acc, rw0, gid, tg);
    }

    // ---- output: acc += h @ W1 ----
    for (int c = 0; c < 4; c++) {
        __syncthreads();
        fillB_g(BhU, BlU, g_BoutH, g_BoutL, c * 32, tid);
        __syncthreads();
        mma_chunk<68>(HhU + 16 * c, HlU + 16 * c, BhU, BlU, acc, rw0, gid, tg);
    }

    // ---- + b1, LayerNorm, write other buffer ----
    float s1e = 0.f, s2e = 0.f, s1o = 0.f, s2o = 0.f;
#pragma unroll
    for (int t = 0; t < 16; t++) {
        int col = 8 * t + 2 * tg;
        float2 bb = *(const float2*)(b1 + col);
        acc[t][0] += bb.x; acc[t][1] += bb.y;
        acc[t][2] += bb.x; acc[t][3] += bb.y;
        s1e += acc[t][0] + acc[t][1];
        s2e += acc[t][0] * acc[t][0] + acc[t][1] * acc[t][1];
        s1o += acc[t][2] + acc[t][3];
        s2o += acc[t][2] * acc[t][2] + acc[t][3] * acc[t][3];
    }
#pragma unroll
    for (int off = 1; off <= 2; off <<= 1) {
        s1e += __shfl_xor_sync(0xffffffffu, s1e, off);
        s2e += __shfl_xor_sync(0xffffffffu, s2e, off);
        s1o += __shfl_xor_sync(0xffffffffu, s1o, off);
        s2o += __shfl_xor_sync(0xffffffffu, s2o, off);
    }
    float mu_e = s1e * (1.f / 128.f);
    float mu_o = s1o * (1.f / 128.f);
    float inv_e = rsqrtf(s2e * (1.f / 128.f) - mu_e * mu_e + LN_EPS);
    float inv_o = rsqrtf(s2o * (1.f / 128.f) - mu_o * mu_o + LN_EPS);

#pragma unroll
    for (int t = 0; t < 16; t++) {
        int col = 8 * t + 2 * tg;
        float2 gv = *(const float2*)(lng + col);
        float2 bv = *(const float2*)(lnb + col);
        if (r_e < NN) {
            float2 o;
            o.x = (acc[t][0] - mu_e) * inv_e * gv.x + bv.x;
            o.y = (acc[t][1] - mu_e) * inv_e * gv.y + bv.y;
            *(float2*)(nnxt + (long)r_e * HDIM + col) = o;
        }
        if (r_o < NN) {
            float2 o;
            o.x = (acc[t][2] - mu_o) * inv_o * gv.x + bv.x;
            o.y = (acc[t][3] - mu_o) * inv_o * gv.y + bv.y;
            *(float2*)(nnxt + (long)r_o * HDIM + col) = o;
        }
    }
}

// ===========================================================================
// MMA decoder: out = relu(n @ W0 + b0) @ W1 + b1    out: [NN,2]
// ===========================================================================
#define D_AH 0
#define D_AL (D_AH + 128 * BST)
#define D_BH (D_AL + 128 * BST)
#define D_BL (D_BH + 128 * BST)
#define D_HO (D_BL + 128 * BST)                 // fp32 h, [128][132]
#define D_W1 (D_HO + 128 * 132)                 // 256 floats
#define D_B1 (D_W1 + 256)                       // 2 floats
#define SM_DECM ((D_B1 + 2) * 4)                // 109576 B

__global__ void __launch_bounds__(256, 2) k_dec_mma(
        const float* __restrict__ b0,
        const float* __restrict__ W1, const float* __restrict__ b1,
        float* __restrict__ out, int par) {
    extern __shared__ uint32 smu[];
    uint32* AhU = smu + D_AH;
    uint32* AlU = smu + D_AL;
    uint32* BhU = smu + D_BH;
    uint32* BlU = smu + D_BL;
    float*  Hout = (float*)(smu + D_HO);
    float*  w1_s = (float*)(smu + D_W1);
    float*  b1_s = (float*)(smu + D_B1);

    const float* nsrc = (par == 0) ? g_n0 : g_n1;

    const int tid = threadIdx.x;
    const int w = tid >> 5, lane = tid & 31;
    const int gid = lane >> 2, tg = lane & 3;
    const int rw0 = w * 16;
    const int row0 = blockIdx.x * 128;
    const int r_e = row0 + rw0 + gid;
    const int r_o = r_e + 8;

    w1_s[tid] = W1[tid];
    if (tid < 2) b1_s[tid] = b1[tid];

    float acc[16][4];
#pragma unroll
    for (int t = 0; t < 16; t++) {
        int col = 8 * t + 2 * tg;
        float2 bb = *(const float2*)(b0 + col);
        acc[t][0] = bb.x; acc[t][1] = bb.y;
        acc[t][2] = bb.x; acc[t][3] = bb.y;
    }
    for (int c = 0; c < 4; c++) {
        __syncthreads();
        fillA(AhU, AlU, nsrc, row0, c * 32, tid);
        fillB_g(BhU, BlU, g_BdecH, g_BdecL, c * 32, tid);
        __syncthreads();
        mma_chunk<BST>(AhU, AlU, BhU, BlU, acc, rw0, gid, tg);
    }

    // relu -> fp32 smem
#pragma unroll
    for (int t = 0; t < 16; t++) {
        int col = 8 * t + 2 * tg;
        *(float2*)(Hout + (rw0 + gid)     * 132 + col) =
            make_float2(fmaxf(acc[t][0], 0.f), fmaxf(acc[t][1], 0.f));
        *(float2*)(Hout + (rw0 + gid + 8) * 132 + col) =
            make_float2(fmaxf(acc[t][2], 0.f), fmaxf(acc[t][3], 0.f));
    }
    __syncthreads();

    // tail: 128 rows x 2 outputs, one thread each
    {
        int row = tid >> 1, c = tid & 1;
        float s = b1_s[c];
#pragma unroll 8
        for (int k = 0; k < 128; k++)
            s = fmaf(Hout[row * 132 + k], w1_s[k * 2 + c], s);
        int gr = row0 + row;
        if (gr < NN) out[gr * 2 + c] = s;
    }
}

// ---------------------------------------------------------------------------
extern "C" void kernel_launch(void* const* d_in, const int* in_sizes, int n_in,
                              void* d_out, int out_size) {
    const float* nodes   = (const float*)d_in[0];
    const float* edges   = (const float*)d_in[1];
    const int*   senders = (const int*)  d_in[2];
    const int*   recvs   = (const int*)  d_in[3];
    const float* enW0 = (const float*)d_in[4];
    const float* enb0 = (const float*)d_in[5];
    const float* enW1 = (const float*)d_in[6];
    const float* enb1 = (const float*)d_in[7];
    const float* eeW0 = (const float*)d_in[8];
    const float* eeb0 = (const float*)d_in[9];
    const float* eeW1 = (const float*)d_in[10];
    const float* eeb1 = (const float*)d_in[11];
    const float* Wmsg = (const float*)d_in[12];
    const float* nW0  = (const float*)d_in[13];
    const float* nb0  = (const float*)d_in[14];
    const float* nW1  = (const float*)d_in[15];
    const float* nb1  = (const float*)d_in[16];
    const float* Wnode= (const float*)d_in[17];
    const float* lng  = (const float*)d_in[18];
    const float* lnb  = (const float*)d_in[19];
    const float* dW0  = (const float*)d_in[20];
    const float* db0  = (const float*)d_in[21];
    const float* dW1  = (const float*)d_in[22];
    const float* db1  = (const float*)d_in[23];
    float* out = (float*)d_out;

    cudaFuncSetAttribute(k_node_enc_mma, cudaFuncAttributeMaxDynamicSharedMemorySize, SM_ENC2);
    cudaFuncSetAttribute(k_edge_mma,     cudaFuncAttributeMaxDynamicSharedMemorySize, SM_EDGE);
    cudaFuncSetAttribute(k_cagg_mma,     cudaFuncAttributeMaxDynamicSharedMemorySize, SM_CAG);
    cudaFuncSetAttribute(k_node_upd_mma, cudaFuncAttributeMaxDynamicSharedMemorySize, SM_MMA);
    cudaFuncSetAttribute(k_dec_mma,      cudaFuncAttributeMaxDynamicSharedMemorySize, SM_DECM);

    // Folds, splits, CSR build, invariants
    k_fold1<<<129, 128>>>(eeW1, eeb1, Wmsg);
    k_fold2<<<257, 128>>>(nW0, Wmsg);
    k_splitB<<<320, 256>>>(nW0, Wnode, nW1, enW1, dW0);
    k_splitE<<<24, 256>>>(eeW0, enW0);
    k_zero_pre<<<(NN * 32 + NN / 4 + 255) / 256, 256>>>();
    k_hist<<<(NEDGE + 255) / 256, 256>>>(recvs);
    k_scan<<<1, 1024>>>();
    k_fillcsr<<<(NEDGE + 255) / 256, 256>>>(senders, recvs);
    k_node_enc_mma<<<NT128, 256, SM_ENC2>>>(nodes, enb0, enb1);
    k_edge_mma<<<ET128, 256, SM_EDGE>>>(edges, eeb0, recvs);
    k_cagg_mma<<<NT128, 256, SM_CAG>>>();

    for (int p = 0; p < NPASS; p++)
        k_node_upd_mma<<<NT128, 256, SM_MMA>>>(nb0, nb1, lng, lnb, p & 1);

    k_dec_mma<<<NT128, 256, SM_DECM>>>(db0, dW1, db1, out, NPASS & 1);
}

// round 16
// speedup vs baseline: 1.0140x; 1.0140x over previous
#include <cuda_runtime.h>
#include <cuda_bf16.h>
#include <math.h>

#define NN     50000
#define NEDGE  600000
#define HDIM   128
#define NPASS  5
#define LN_EPS 1e-6f

#define NT128      ((NN + 127) / 128)    // 391  (mma tiles, nodes)
#define ET128      ((NEDGE + 127) / 128) // 4688 (mma tiles, edges)

typedef unsigned int uint32;
typedef unsigned short ushort16;

// Persistent device scratch — double-buffered node features
__device__ float g_n0[NN * HDIM];
__device__ float g_n1[NN * HDIM];
__device__ float g_hsum[NN * HDIM];
__device__ float g_cagg[NN * HDIM];
__device__ float g_T1[HDIM * HDIM];     // W1e @ Wm_bot
__device__ float g_tvec[HDIM];          // b1e @ Wm_bot
__device__ float g_bg[HDIM];

// Receiver-CSR of the edge list (built once per launch)
__device__ int g_rowptr[NN + 1];
__device__ int g_cursor[NN];
__device__ int g_col[NEDGE];

// Split-bf16 weight tables, [N][K] k-contiguous (transposed)
__device__ __align__(16) ushort16 g_BtopH[HDIM * HDIM], g_BtopL[HDIM * HDIM]; // W0_top
__device__ __align__(16) ushort16 g_BWfH [HDIM * HDIM], g_BWfL [HDIM * HDIM]; // Wm_top@W0_bot
__device__ __align__(16) ushort16 g_BresH[HDIM * HDIM], g_BresL[HDIM * HDIM]; // Wn
__device__ __align__(16) ushort16 g_BoutH[HDIM * HDIM], g_BoutL[HDIM * HDIM]; // W1
__device__ __align__(16) ushort16 g_Ben1H[HDIM * HDIM], g_Ben1L[HDIM * HDIM]; // enc W1
__device__ __align__(16) ushort16 g_BWgH[HDIM * HDIM],  g_BWgL[HDIM * HDIM];  // (W1e@Wm_bot)@W0_bot
__device__ __align__(16) ushort16 g_BdecH[HDIM * HDIM], g_BdecL[HDIM * HDIM]; // dec W0
__device__ __align__(16) ushort16 g_BeH[HDIM * 16],   g_BeL[HDIM * 16];       // edge W0 [n][16k]
__device__ __align__(16) ushort16 g_Ben0H[HDIM * 32], g_Ben0L[HDIM * 32];     // enc W0 [n][32k]

// ---------------------------------------------------------------------------
// bf16 helpers + MMA
// ---------------------------------------------------------------------------
__device__ __forceinline__ uint32 pack_bf2(float x, float y) {
    __nv_bfloat162 t = __floats2bfloat162_rn(x, y);
    return *reinterpret_cast<uint32*>(&t);
}
__device__ __forceinline__ void split_bf(float v, ushort16& h, ushort16& l) {
    __nv_bfloat16 hb = __float2bfloat16_rn(v);
    float lo = v - __bfloat162float(hb);
    __nv_bfloat16 lb = __float2bfloat16_rn(lo);
    h = *reinterpret_cast<ushort16*>(&hb);
    l = *reinterpret_cast<ushort16*>(&lb);
}
__device__ __forceinline__ void split_pack2(float2 v, uint32& h, uint32& l) {
    float ex = __bfloat162float(__float2bfloat16_rn(v.x));
    float ey = __bfloat162float(__float2bfloat16_rn(v.y));
    h = pack_bf2(v.x, v.y);
    l = pack_bf2(v.x - ex, v.y - ey);
}
#define MMA16816(d, a0,a1,a2,a3, b0,b1) \
    asm volatile("mma.sync.aligned.m16n8k16.row.col.f32.bf16.bf16.f32 " \
        "{%0,%1,%2,%3},{%4,%5,%6,%7},{%8,%9},{%0,%1,%2,%3};" \
        : "+f"((d)[0]), "+f"((d)[1]), "+f"((d)[2]), "+f"((d)[3]) \
        : "r"(a0), "r"(a1), "r"(a2), "r"(a3), "r"(b0), "r"(b1))

// ---------------------------------------------------------------------------
// k_prep: fold1 + 5x splitB + splitE + zero(hsum, cursor), blockIdx dispatch
// NOTE (R15 lesson): the splitE branch must use the ENCODER W0 (enW0), not
// the process-block nW0 — parameters are kept distinct below.
// ---------------------------------------------------------------------------
#define PREP_F1   129
#define PREP_SB   (PREP_F1 + 320)
#define PREP_SE   (PREP_SB + 24)
#define PREP_Z    (PREP_SE + 6300)

__global__ void k_prep(const float* __restrict__ W1e, const float* __restrict__ b1e,
                       const float* __restrict__ Wm,
                       const float* __restrict__ W0n, const float* __restrict__ Wnode,
                       const float* __restrict__ W1n, const float* __restrict__ We1,
                       const float* __restrict__ Wd0,
                       const float* __restrict__ W0e,
                       const float* __restrict__ We0) {   // encoder node W0 [32][128]
    __shared__ float a[HDIM];
    int bid = blockIdx.x;
    int tid = threadIdx.x;

    if (bid < PREP_F1) {
        // fold1: T1 = W1e @ Wm_bot (row bid), tvec = b1e @ Wm_bot
        int j = tid & 127;
        a[j] = (bid < 128) ? W1e[bid * HDIM + j] : b1e[j];
        __syncthreads();
        if (tid < 128) {
            float s = 0.f;
#pragma unroll 8
            for (int l = 0; l < HDIM; l++)
                s = fmaf(a[l], Wm[(HDIM + l) * HDIM + j], s);
            if (bid < 128) g_T1[bid * HDIM + j] = s;
            else           g_tvec[j] = s;
        }
    } else if (bid < PREP_SB) {
        int b = bid - PREP_F1;
        int which = b >> 6;
        const float* W; ushort16* dH; ushort16* dL;
        if (which == 0)      { W = W0n;   dH = g_BtopH; dL = g_BtopL; }
        else if (which == 1) { W = Wnode; dH = g_BresH; dL = g_BresL; }
        else if (which == 2) { W = W1n;   dH = g_BoutH; dL = g_BoutL; }
        else if (which == 3) { W = We1;   dH = g_Ben1H; dL = g_Ben1L; }
        else                 { W = Wd0;   dH = g_BdecH; dL = g_BdecL; }
        int idx = (b & 63) * 256 + tid;
        int k = idx >> 7, n = idx & 127;
        ushort16 h, l;
        split_bf(W[k * HDIM + n], h, l);
        dH[n * HDIM + k] = h;
        dL[n * HDIM + k] = l;
    } else if (bid < PREP_SE) {
        int idx = (bid - PREP_SB) * 256 + tid;   // 2048 + 4096
        if (idx < 2048) {
            int n = idx & 127, k = idx >> 7;
            ushort16 h, l;
            split_bf(W0e[k * HDIM + n], h, l);
            g_BeH[n * 16 + k] = h;
            g_BeL[n * 16 + k] = l;
        } else if (idx < 6144) {
            int i = idx - 2048;
            int n = i & 127, k = i >> 7;
            ushort16 h, l;
            split_bf(We0[k * HDIM + n], h, l);   // FIXED: encoder W0, not nW0
            g_Ben0H[n * 32 + k] = h;
            g_Ben0L[n * 32 + k] = l;
        }
    } else if (bid < PREP_Z) {
        int i = (bid - PREP_SE) * 256 + tid;
        if (i < NN * 32) ((float4*)g_hsum)[i] = make_float4(0.f, 0.f, 0.f, 0.f);
        else {
            int d = i - NN * 32;
            if (d < NN / 4) ((int4*)g_cursor)[d] = make_int4(0, 0, 0, 0);
        }
    }
}

// fold2: bid<128: Wg row bid (split); bid==128: bg; bid>=129: Wf row (split)
__global__ void k_fold2(const float* __restrict__ W0n, const float* __restrict__ Wm) {
    __shared__ float a[HDIM];
    int j = threadIdx.x;
    int bid = blockIdx.x;
    if (bid < 128)       a[j] = g_T1[bid * HDIM + j];
    else if (bid == 128) a[j] = g_tvec[j];
    else                 a[j] = Wm[(bid - 129) * HDIM + j];
    __syncthreads();
    float s = 0.f;
#pragma unroll 8
    for (int l = 0; l < HDIM; l++)
        s = fmaf(a[l], W0n[(HDIM + l) * HDIM + j], s);
    if (bid < 128) {
        ushort16 h, l2; split_bf(s, h, l2);
        g_BWgH[j * HDIM + bid] = h;
        g_BWgL[j * HDIM + bid] = l2;
    } else if (bid == 128) g_bg[j] = s;
    else {
        int k = bid - 129;
        ushort16 h, l2; split_bf(s, h, l2);
        g_BWfH[j * HDIM + k] = h;
        g_BWfL[j * HDIM + k] = l2;
    }
}

// ---------------------------------------------------------------------------
// CSR build
// ---------------------------------------------------------------------------
__global__ void k_hist(const int* __restrict__ recvs) {
    int e = blockIdx.x * 256 + threadIdx.x;
    if (e < NEDGE) atomicAdd(g_cursor + recvs[e], 1);
}

__global__ void __launch_bounds__(1024) k_scan() {
    __shared__ int partial[1024];
    const int CHUNK = (NN + 1023) / 1024;
    int t = threadIdx.x;
    int beg = t * CHUNK, end = min(beg + CHUNK, NN);
    int s = 0;
    for (int i = beg; i < end; i++) s += g_cursor[i];
    partial[t] = s;
    __syncthreads();
    for (int off = 1; off < 1024; off <<= 1) {
        int v = (t >= off) ? partial[t - off] : 0;
        __syncthreads();
        partial[t] += v;
        __syncthreads();
    }
    int base = (t > 0) ? partial[t - 1] : 0;
    for (int i = beg; i < end; i++) {
        int c = g_cursor[i];
        g_rowptr[i] = base;
        g_cursor[i] = base;
        base += c;
    }
    if (t == 1023) g_rowptr[NN] = partial[1023];
}

__global__ void k_fillcsr(const int* __restrict__ senders,
                          const int* __restrict__ recvs) {
    int e = blockIdx.x * 256 + threadIdx.x;
    if (e < NEDGE) {
        int pos = atomicAdd(g_cursor + recvs[e], 1);
        g_col[pos] = senders[e];
    }
}

// ===========================================================================
// Shared MMA building blocks
// ===========================================================================
#define BST 20

__device__ __forceinline__ void fillB_g(uint32* BhU, uint32* BlU,
                                        const ushort16* __restrict__ gH,
                                        const ushort16* __restrict__ gL,
                                        int koff, int tid) {
    const uint4* sH = (const uint4*)gH;
    const uint4* sL = (const uint4*)gL;
    int kq0 = koff >> 3;
#pragma unroll
    for (int i = 0; i < 2; i++) {
        int p = tid + i * 256;
        int n = p >> 2, kq = p & 3;
        *(uint4*)(BhU + n * BST + 4 * kq) = sH[n * 16 + kq0 + kq];
        *(uint4*)(BlU + n * BST + 4 * kq) = sL[n * 16 + kq0 + kq];
    }
}

__device__ __forceinline__ void fillA(uint32* AhU, uint32* AlU,
                                      const float* __restrict__ src,
                                      int row0, int koff, int tid) {
#pragma unroll
    for (int i = 0; i < 4; i++) {
        int p = tid + i * 256;
        int row = p >> 3, q = p & 7;
        int gr = row0 + row;
        float4 v = make_float4(0.f, 0.f, 0.f, 0.f);
        if (gr < NN) v = *(const float4*)(src + (long)gr * HDIM + koff + 4 * q);
        float ex = __bfloat162float(__float2bfloat16_rn(v.x));
        float ey = __bfloat162float(__float2bfloat16_rn(v.y));
        float ez = __bfloat162float(__float2bfloat16_rn(v.z));
        float ew = __bfloat162float(__float2bfloat16_rn(v.w));
        uint2 hh = make_uint2(pack_bf2(v.x, v.y), pack_bf2(v.z, v.w));
        uint2 ll = make_uint2(pack_bf2(v.x - ex, v.y - ey), pack_bf2(v.z - ez, v.w - ew));
        *(uint2*)(AhU + row * BST + 2 * q) = hh;
        *(uint2*)(AlU + row * BST + 2 * q) = ll;
    }
}

template<int AS>
__device__ __forceinline__ void mma_chunk(const uint32* AhU, const uint32* AlU,
                                          const uint32* BhU, const uint32* BlU,
                                          float acc[16][4], int rw0, int gid, int tg) {
#pragma unroll
    for (int kb2 = 0; kb2 <= 8; kb2 += 8) {
        int a0i = (rw0 + gid) * AS + kb2 + tg;
        int a1i = a0i + 8 * AS;
        uint32 ah0 = AhU[a0i],     ah1 = AhU[a1i];
        uint32 ah2 = AhU[a0i + 4], ah3 = AhU[a1i + 4];
        uint32 al0 = AlU[a0i],     al1 = AlU[a1i];
        uint32 al2 = AlU[a0i + 4], al3 = AlU[a1i + 4];
#pragma unroll
        for (int t = 0; t < 16; t++) {
            int bi = (8 * t + gid) * BST + kb2 + tg;
            uint32 bh0 = BhU[bi], bh1 = BhU[bi + 4];
            uint32 bl0 = BlU[bi], bl1 = BlU[bi + 4];
            MMA16816(acc[t], ah0, ah1, ah2, ah3, bh0, bh1);
            MMA16816(acc[t], ah0, ah1, ah2, ah3, bl0, bl1);
            MMA16816(acc[t], al0, al1, al2, al3, bh0, bh1);
        }
    }
}

// ===========================================================================
// Merged MMA encoder kernel: blocks [0, NT128) encode nodes; [NT128, +ET128)
// encode edges + scatter to g_hsum.
// ===========================================================================
#define E_BH 0
#define E_BL (E_BH + 128 * BST)
#define E_HH (E_BL + 128 * BST)
#define E_HL (E_HH + 128 * 68)
#define SM_ENC2 ((E_HL + 128 * 68) * 4)    // 90112 B (>= edge path's 75776)

__global__ void __launch_bounds__(256, 2) k_enc_all_mma(
        const float* __restrict__ xn,
        const float* __restrict__ nb0, const float* __restrict__ nb1,
        const float* __restrict__ xe, const float* __restrict__ eb0,
        const int* __restrict__ recvs) {
    extern __shared__ uint32 smu[];

    const int tid = threadIdx.x;
    const int w = tid >> 5, lane = tid & 31;
    const int gid = lane >> 2, tg = lane & 3;
    const int rw0 = w * 16;

    if (blockIdx.x < NT128) {
        // ---------------- node encoder path ----------------
        uint32* BhU = smu + E_BH;
        uint32* BlU = smu + E_BL;
        uint32* HhU = smu + E_HH;
        uint32* HlU = smu + E_HL;

        const int row0 = blockIdx.x * 128;
        const int r_e = row0 + rw0 + gid;
        const int r_o = r_e + 8;

#pragma unroll
        for (int i = 0; i < 2; i++) {
            int p = tid + i * 256;   // 512 uint4
            *(uint4*)(BhU + 4 * p) = ((const uint4*)g_Ben0H)[p];
            *(uint4*)(BlU + 4 * p) = ((const uint4*)g_Ben0L)[p];
        }

        float2 z = make_float2(0.f, 0.f);
        uint32 ah[2][4], al[2][4];
#pragma unroll
        for (int kb = 0; kb < 2; kb++) {
            float2 vE0 = (r_e < NN) ? *(const float2*)(xn + (long)r_e * 32 + kb * 16 + 2 * tg)     : z;
            float2 vO0 = (r_o < NN) ? *(const float2*)(xn + (long)r_o * 32 + kb * 16 + 2 * tg)     : z;
            float2 vE1 = (r_e < NN) ? *(const float2*)(xn + (long)r_e * 32 + kb * 16 + 8 + 2 * tg) : z;
            float2 vO1 = (r_o < NN) ? *(const float2*)(xn + (long)r_o * 32 + kb * 16 + 8 + 2 * tg) : z;
            split_pack2(vE0, ah[kb][0], al[kb][0]);
            split_pack2(vO0, ah[kb][1], al[kb][1]);
            split_pack2(vE1, ah[kb][2], al[kb][2]);
            split_pack2(vO1, ah[kb][3], al[kb][3]);
        }
        __syncthreads();

        float acc[16][4];
#pragma unroll
        for (int t = 0; t < 16; t++) {
            int col = 8 * t + 2 * tg;
            float2 bb = *(const float2*)(nb0 + col);
            acc[t][0] = bb.x; acc[t][1] = bb.y;
            acc[t][2] = bb.x; acc[t][3] = bb.y;
        }
#pragma unroll
        for (int kb = 0; kb < 2; kb++) {
#pragma unroll
            for (int t = 0; t < 16; t++) {
                int bi = (8 * t + gid) * 16 + kb * 8 + tg;
                uint32 bh0 = BhU[bi], bh1 = BhU[bi + 4];
                uint32 bl0 = BlU[bi], bl1 = BlU[bi + 4];
                MMA16816(acc[t], ah[kb][0], ah[kb][1], ah[kb][2], ah[kb][3], bh0, bh1);
                MMA16816(acc[t], ah[kb][0], ah[kb][1], ah[kb][2], ah[kb][3], bl0, bl1);
                MMA16816(acc[t], al[kb][0], al[kb][1], al[kb][2], al[kb][3], bh0, bh1);
            }
        }

#pragma unroll
        for (int t = 0; t < 16; t++) {
            float h0 = fmaxf(acc[t][0], 0.f), h1 = fmaxf(acc[t][1], 0.f);
            float h2 = fmaxf(acc[t][2], 0.f), h3 = fmaxf(acc[t][3], 0.f);
            int ie = (rw0 + gid) * 68 + 4 * t + tg;
            int io = ie + 8 * 68;
            uint32 hh, ll;
            split_pack2(make_float2(h0, h1), hh, ll);
            HhU[ie] = hh; HlU[ie] = ll;
            split_pack2(make_float2(h2, h3), hh, ll);
            HhU[io] = hh; HlU[io] = ll;
        }

#pragma unroll
        for (int t = 0; t < 16; t++) {
            int col = 8 * t + 2 * tg;
            float2 bb = *(const float2*)(nb1 + col);
            acc[t][0] = bb.x; acc[t][1] = bb.y;
            acc[t][2] = bb.x; acc[t][3] = bb.y;
        }
        for (int c = 0; c < 4; c++) {
            __syncthreads();
            fillB_g(BhU, BlU, g_Ben1H, g_Ben1L, c * 32, tid);
            __syncthreads();
            mma_chunk<68>(HhU + 16 * c, HlU + 16 * c, BhU, BlU, acc, rw0, gid, tg);
        }

#pragma unroll
        for (int t = 0; t < 16; t++) {
            int col = 8 * t + 2 * tg;
            if (r_e < NN)
                *(float2*)(g_n0 + (long)r_e * HDIM + col) = make_float2(acc[t][0], acc[t][1]);
            if (r_o < NN)
                *(float2*)(g_n0 + (long)r_o * HDIM + col) = make_float2(acc[t][2], acc[t][3]);
        }
    } else {
        // ---------------- edge encoder + scatter path ----------------
        uint32* BhU  = smu;
        uint32* BlU  = smu + 1024;
        float*  Hout = (float*)(smu + 2048);

        const int row0 = (blockIdx.x - NT128) * 128;
        const int eE = row0 + rw0 + gid;
        const int eO = eE + 8;

#pragma unroll
        for (int i = 0; i < 4; i++) {
            int p = tid + i * 256;
            BhU[p] = ((const uint32*)g_BeH)[p];
            BlU[p] = ((const uint32*)g_BeL)[p];
        }

        float2 z = make_float2(0.f, 0.f);
        float2 vE0 = (eE < NEDGE) ? *(const float2*)(xe + (long)eE * 16 + 2 * tg)     : z;
        float2 vE1 = (eE < NEDGE) ? *(const float2*)(xe + (long)eE * 16 + 8 + 2 * tg) : z;
        float2 vO0 = (eO < NEDGE) ? *(const float2*)(xe + (long)eO * 16 + 2 * tg)     : z;
        float2 vO1 = (eO < NEDGE) ? *(const float2*)(xe + (long)eO * 16 + 8 + 2 * tg) : z;
        uint32 ah0, al0, ah1, al1, ah2, al2, ah3, al3;
        split_pack2(vE0, ah0, al0);
        split_pack2(vO0, ah1, al1);
        split_pack2(vE1, ah2, al2);
        split_pack2(vO1, ah3, al3);
        __syncthreads();

        float acc[16][4];
#pragma unroll
        for (int t = 0; t < 16; t++) {
            int col = 8 * t + 2 * tg;
            float2 bb = *(const float2*)(eb0 + col);
            acc[t][0] = bb.x; acc[t][1] = bb.y;
            acc[t][2] = bb.x; acc[t][3] = bb.y;
        }
#pragma unroll
        for (int t = 0; t < 16; t++) {
            int bi = (8 * t + gid) * 8 + tg;
            uint32 bh0 = BhU[bi], bh1 = BhU[bi + 4];
            uint32 bl0 = BlU[bi], bl1 = BlU[bi + 4];
            MMA16816(acc[t], ah0, ah1, ah2, ah3, bh0, bh1);
            MMA16816(acc[t], ah0, ah1, ah2, ah3, bl0, bl1);
            MMA16816(acc[t], al0, al1, al2, al3, bh0, bh1);
        }

#pragma unroll
        for (int t = 0; t < 16; t++) {
            int col = 8 * t + 2 * tg;
            *(float2*)(Hout + (rw0 + gid)     * 132 + col) =
                make_float2(fmaxf(acc[t][0], 0.f), fmaxf(acc[t][1], 0.f));
            *(float2*)(Hout + (rw0 + gid + 8) * 132 + col) =
                make_float2(fmaxf(acc[t][2], 0.f), fmaxf(acc[t][3], 0.f));
        }
        __syncthreads();

        int j = lane * 4;
        for (int r = 0; r < 16; r++) {
            int e = row0 + rw0 + r;
            if (e < NEDGE) {
                int rv = __ldg(recvs + e);
                float4 v = *(const float4*)(Hout + (rw0 + r) * 132 + j);
                float* dst = g_hsum + (long)rv * HDIM + j;
                asm volatile("red.global.add.v4.f32 [%0], {%1, %2, %3, %4};"
                             :: "l"(dst), "f"(v.x), "f"(v.y), "f"(v.z), "f"(v.w) : "memory");
            }
        }
    }
}

// ===========================================================================
// MMA cagg: c_agg = g_hsum @ Wg + deg * bg
// ===========================================================================
#define SM_CAG (4 * 128 * BST * 4)     // 40960 B

__global__ void __launch_bounds__(256, 2) k_cagg_mma() {
    extern __shared__ uint32 smu[];
    uint32* AhU = smu;
    uint32* AlU = smu + 128 * BST;
    uint32* BhU = smu + 2 * 128 * BST;
    uint32* BlU = smu + 3 * 128 * BST;

    const int tid = threadIdx.x;
    const int w = tid >> 5, lane = tid & 31;
    const int gid = lane >> 2, tg = lane & 3;
    const int rw0 = w * 16;
    const int row0 = blockIdx.x * 128;
    const int r_e = row0 + rw0 + gid;
    const int r_o = r_e + 8;

    float acc[16][4];
    {
        float de = (r_e < NN) ? (float)(g_rowptr[r_e + 1] - g_rowptr[r_e]) : 0.f;
        float dd = (r_o < NN) ? (float)(g_rowptr[r_o + 1] - g_rowptr[r_o]) : 0.f;
#pragma unroll
        for (int t = 0; t < 16; t++) {
            int col = 8 * t + 2 * tg;
            float2 bb = *(const float2*)(g_bg + col);
            acc[t][0] = de * bb.x; acc[t][1] = de * bb.y;
            acc[t][2] = dd * bb.x; acc[t][3] = dd * bb.y;
        }
    }
    for (int c = 0; c < 4; c++) {
        __syncthreads();
        fillA(AhU, AlU, g_hsum, row0, c * 32, tid);
        fillB_g(BhU, BlU, g_BWgH, g_BWgL, c * 32, tid);
        __syncthreads();
        mma_chunk<BST>(AhU, AlU, BhU, BlU, acc, rw0, gid, tg);
    }
#pragma unroll
    for (int t = 0; t < 16; t++) {
        int col = 8 * t + 2 * tg;
        if (r_e < NN)
            *(float2*)(g_cagg + (long)r_e * HDIM + col) = make_float2(acc[t][0], acc[t][1]);
        if (r_o < NN)
            *(float2*)(g_cagg + (long)r_o * HDIM + col) = make_float2(acc[t][2], acc[t][3]);
    }
}

// ===========================================================================
// Fused MMA node update (CSR gather with row-paired MLP8) — R13 proven
// ===========================================================================
#define U_AH 0
#define U_AL (U_AH + 128 * BST)
#define U_BH (U_AL + 128 * BST)
#define U_BL (U_BH + 128 * BST)
#define U_HH (U_BL + 128 * BST)
#define U_HL (U_HH + 128 * 68)
#define U_END (U_HL + 128 * 68)
#define SM_MMA (U_END * 4)          // 110592 bytes

__global__ void __launch_bounds__(256, 2) k_node_upd_mma(
        const float* __restrict__ b0, const float* __restrict__ b1,
        const float* __restrict__ lng, const float* __restrict__ lnb,
        int par) {
    extern __shared__ uint32 smu[];
    uint32* AhU = smu + U_AH;
    uint32* AlU = smu + U_AL;
    uint32* BhU = smu + U_BH;
    uint32* BlU = smu + U_BL;
    uint32* HhU = smu + U_HH;
    uint32* HlU = smu + U_HL;

    const float* ncur = (par == 0) ? g_n0 : g_n1;
    float*       nnxt = (par == 0) ? g_n1 : g_n0;

    const int tid = threadIdx.x;
    const int w = tid >> 5, lane = tid & 31;
    const int gid = lane >> 2, tg = lane & 3;
    const int rw0 = w * 16;
    const int row0 = blockIdx.x * 128;
    const int r_e = row0 + rw0 + gid;
    const int r_o = r_e + 8;
    const int jj = lane * 4;

    // ---- CSR gather, row-paired (rr, rr+8) for MLP8 ----
    for (int rr = 0; rr < 8; rr++) {
        int rowA = rw0 + rr, rowB = rowA + 8;
        int grA = row0 + rowA, grB = row0 + rowB;
        float A0 = 0.f, A1 = 0.f, A2 = 0.f, A3 = 0.f;
        float B0 = 0.f, B1 = 0.f, B2 = 0.f, B3 = 0.f;
        int eA = 0, nA = 0, eB = 0, nB = 0;
        if (grA < NN) { eA = g_rowptr[grA]; nA = g_rowptr[grA + 1]; }
        if (grB < NN) { eB = g_rowptr[grB]; nB = g_rowptr[grB + 1]; }
        while (eA + 4 <= nA && eB + 4 <= nB) {
            int a0 = g_col[eA], a1 = g_col[eA+1], a2 = g_col[eA+2], a3 = g_col[eA+3];
            int b0i = g_col[eB], b1i = g_col[eB+1], b2i = g_col[eB+2], b3i = g_col[eB+3];
            float4 u0 = *(const float4*)(ncur + (long)a0 * HDIM + jj);
            float4 u1 = *(const float4*)(ncur + (long)a1 * HDIM + jj);
            float4 u2 = *(const float4*)(ncur + (long)a2 * HDIM + jj);
            float4 u3 = *(const float4*)(ncur + (long)a3 * HDIM + jj);
            float4 w0 = *(const float4*)(ncur + (long)b0i * HDIM + jj);
            float4 w1 = *(const float4*)(ncur + (long)b1i * HDIM + jj);
            float4 w2 = *(const float4*)(ncur + (long)b2i * HDIM + jj);
            float4 w3 = *(const float4*)(ncur + (long)b3i * HDIM + jj);
            A0 += u0.x + u1.x + u2.x + u3.x;
            A1 += u0.y + u1.y + u2.y + u3.y;
            A2 += u0.z + u1.z + u2.z + u3.z;
            A3 += u0.w + u1.w + u2.w + u3.w;
            B0 += w0.x + w1.x + w2.x + w3.x;
            B1 += w0.y + w1.y + w2.y + w3.y;
            B2 += w0.z + w1.z + w2.z + w3.z;
            B3 += w0.w + w1.w + w2.w + w3.w;
            eA += 4; eB += 4;
        }
        for (; eA + 4 <= nA; eA += 4) {
            int a0 = g_col[eA], a1 = g_col[eA+1], a2 = g_col[eA+2], a3 = g_col[eA+3];
            float4 u0 = *(const float4*)(ncur + (long)a0 * HDIM + jj);
            float4 u1 = *(const float4*)(ncur + (long)a1 * HDIM + jj);
            float4 u2 = *(const float4*)(ncur + (long)a2 * HDIM + jj);
            float4 u3 = *(const float4*)(ncur + (long)a3 * HDIM + jj);
            A0 += u0.x + u1.x + u2.x + u3.x;
            A1 += u0.y + u1.y + u2.y + u3.y;
            A2 += u0.z + u1.z + u2.z + u3.z;
            A3 += u0.w + u1.w + u2.w + u3.w;
        }
        for (; eA < nA; eA++) {
            int s = g_col[eA];
            float4 v = *(const float4*)(ncur + (long)s * HDIM + jj);
            A0 += v.x; A1 += v.y; A2 += v.z; A3 += v.w;
        }
        for (; eB + 4 <= nB; eB += 4) {
            int b0i = g_col[eB], b1i = g_col[eB+1], b2i = g_col[eB+2], b3i = g_col[eB+3];
            float4 w0 = *(const float4*)(ncur + (long)b0i * HDIM + jj);
            float4 w1 = *(const float4*)(ncur + (long)b1i * HDIM + jj);
            float4 w2 = *(const float4*)(ncur + (long)b2i * HDIM + jj);
            float4 w3 = *(const float4*)(ncur + (long)b3i * HDIM + jj);
            B0 += w0.x + w1.x + w2.x + w3.x;
            B1 += w0.y + w1.y + w2.y + w3.y;
            B2 += w0.z + w1.z + w2.z + w3.z;
            B3 += w0.w + w1.w + w2.w + w3.w;
        }
        for (; eB < nB; eB++) {
            int s = g_col[eB];
            float4 v = *(const float4*)(ncur + (long)s * HDIM + jj);
            B0 += v.x; B1 += v.y; B2 += v.z; B3 += v.w;
        }
        uint32 h0, l0, h1, l1;
        split_pack2(make_float2(A0, A1), h0, l0);
        split_pack2(make_float2(A2, A3), h1, l1);
        *(uint2*)(HhU + rowA * 68 + lane * 2) = make_uint2(h0, h1);
        *(uint2*)(HlU + rowA * 68 + lane * 2) = make_uint2(l0, l1);
        split_pack2(make_float2(B0, B1), h0, l0);
        split_pack2(make_float2(B2, B3), h1, l1);
        *(uint2*)(HhU + rowB * 68 + lane * 2) = make_uint2(h0, h1);
        *(uint2*)(HlU + rowB * 68 + lane * 2) = make_uint2(l0, l1);
    }

    float acc[16][4];

    // ---- hidden accumulator init: b0 + c_agg ----
#pragma unroll
    for (int t = 0; t < 16; t++) {
        int col = 8 * t + 2 * tg;
        float2 bb = *(const float2*)(b0 + col);
        float2 ce = (r_e < NN) ? *(const float2*)(g_cagg + (long)r_e * HDIM + col)
                               : make_float2(0.f, 0.f);
        float2 co = (r_o < NN) ? *(const float2*)(g_cagg + (long)r_o * HDIM + col)
                               : make_float2(0.f, 0.f);
        acc[t][0] = bb.x + ce.x; acc[t][1] = bb.y + ce.y;
        acc[t][2] = bb.x + co.x; acc[t][3] = bb.y + co.y;
    }

    // ---- hidden: K = 256 — n chunks from gmem, S chunks from H ----
    for (int c = 0; c < 8; c++) {
        int koff = (c & 3) * 32;
        __syncthreads();
        if (c < 4) fillA(AhU, AlU, ncur, row0, koff, tid);
        fillB_g(BhU, BlU, (c < 4) ? g_BtopH : g_BWfH,
                          (c < 4) ? g_BtopL : g_BWfL, koff, tid);
        __syncthreads();
        if (c < 4) mma_chunk<BST>(AhU, AlU, BhU, BlU, acc, rw0, gid, tg);
        else       mma_chunk<68>(HhU + 16 * (c - 4), HlU + 16 * (c - 4),
                                 BhU, BlU, acc, rw0, gid, tg);
    }

    // ---- relu + split-store h to smem H ----
    __syncthreads();
#pragma unroll
    for (int t = 0; t < 16; t++) {
        float h0 = fmaxf(acc[t][0], 0.f), h1 = fmaxf(acc[t][1], 0.f);
        float h2 = fmaxf(acc[t][2], 0.f), h3 = fmaxf(acc[t][3], 0.f);
        int ie = (rw0 + gid) * 68 + 4 * t + tg;
        int io = ie + 8 * 68;
        uint32 hh, ll;
        split_pack2(make_float2(h0, h1), hh, ll);
        HhU[ie] = hh; HlU[ie] = ll;
        split_pack2(make_float2(h2, h3), hh, ll);
        HhU[io] = hh; HlU[io] = ll;
    }

    // ---- residual: acc = n @ Wn ----
#pragma unroll
    for (int t = 0; t < 16; t++) {
        acc[t][0] = 0.f; acc[t][1] = 0.f; acc[t][2] = 0.f; acc[t][3] = 0.f;
    }
    for (int c = 0; c < 4; c++) {
        __syncthreads();
        fillA(AhU, AlU, ncur, row0, c * 32, tid);
        fillB_g(BhU, BlU, g_BresH, g_BresL, c * 32, tid);
        __syncthreads();
        mma_chunk<BST>(AhU, AlU, BhU, BlU, acc, rw0, gid, tg);
    }

    // ---- output: acc += h @ W1 ----
    for (int c = 0; c < 4; c++) {
        __syncthreads();
        fillB_g(BhU, BlU, g_BoutH, g_BoutL, c * 32, tid);
        __syncthreads();
        mma_chunk<68>(HhU + 16 * c, HlU + 16 * c, BhU, BlU, acc, rw0, gid, tg);
    }

    // ---- + b1, LayerNorm, write other buffer ----
    float s1e = 0.f, s2e = 0.f, s1o = 0.f, s2o = 0.f;
#pragma unroll
    for (int t = 0; t < 16; t++) {
        int col = 8 * t + 2 * tg;
        float2 bb = *(const float2*)(b1 + col);
        acc[t][0] += bb.x; acc[t][1] += bb.y;
        acc[t][2] += bb.x; acc[t][3] += bb.y;
        s1e += acc[t][0] + acc[t][1];
        s2e += acc[t][0] * acc[t][0] + acc[t][1] * acc[t][1];
        s1o += acc[t][2] + acc[t][3];
        s2o += acc[t][2] * acc[t][2] + acc[t][3] * acc[t][3];
    }
#pragma unroll
    for (int off = 1; off <= 2; off <<= 1) {
        s1e += __shfl_xor_sync(0xffffffffu, s1e, off);
        s2e += __shfl_xor_sync(0xffffffffu, s2e, off);
        s1o += __shfl_xor_sync(0xffffffffu, s1o, off);
        s2o += __shfl_xor_sync(0xffffffffu, s2o, off);
    }
    float mu_e = s1e * (1.f / 128.f);
    float mu_o = s1o * (1.f / 128.f);
    float inv_e = rsqrtf(s2e * (1.f / 128.f) - mu_e * mu_e + LN_EPS);
    float inv_o = rsqrtf(s2o * (1.f / 128.f) - mu_o * mu_o + LN_EPS);

#pragma unroll
    for (int t = 0; t < 16; t++) {
        int col = 8 * t + 2 * tg;
        float2 gv = *(const float2*)(lng + col);
        float2 bv = *(const float2*)(lnb + col);
        if (r_e < NN) {
            float2 o;
            o.x = (acc[t][0] - mu_e) * inv_e * gv.x + bv.x;
            o.y = (acc[t][1] - mu_e) * inv_e * gv.y + bv.y;
            *(float2*)(nnxt + (long)r_e * HDIM + col) = o;
        }
        if (r_o < NN) {
            float2 o;
            o.x = (acc[t][2] - mu_o) * inv_o * gv.x + bv.x;
            o.y = (acc[t][3] - mu_o) * inv_o * gv.y + bv.y;
            *(float2*)(nnxt + (long)r_o * HDIM + col) = o;
        }
    }
}

// ===========================================================================
// MMA decoder: out = relu(n @ W0 + b0) @ W1 + b1    out: [NN,2]
// ===========================================================================
#define D_AH 0
#define D_AL (D_AH + 128 * BST)
#define D_BH (D_AL + 128 * BST)
#define D_BL (D_BH + 128 * BST)
#define D_HO (D_BL + 128 * BST)                 // fp32 h, [128][132]
#define D_W1 (D_HO + 128 * 132)                 // 256 floats
#define D_B1 (D_W1 + 256)                       // 2 floats
#define SM_DECM ((D_B1 + 2) * 4)                // 109576 B

__global__ void __launch_bounds__(256, 2) k_dec_mma(
        const float* __restrict__ b0,
        const float* __restrict__ W1, const float* __restrict__ b1,
        float* __restrict__ out, int par) {
    extern __shared__ uint32 smu[];
    uint32* AhU = smu + D_AH;
    uint32* AlU = smu + D_AL;
    uint32* BhU = smu + D_BH;
    uint32* BlU = smu + D_BL;
    float*  Hout = (float*)(smu + D_HO);
    float*  w1_s = (float*)(smu + D_W1);
    float*  b1_s = (float*)(smu + D_B1);

    const float* nsrc = (par == 0) ? g_n0 : g_n1;

    const int tid = threadIdx.x;
    const int w = tid >> 5, lane = tid & 31;
    const int gid = lane >> 2, tg = lane & 3;
    const int rw0 = w * 16;
    const int row0 = blockIdx.x * 128;
    const int r_e = row0 + rw0 + gid;
    const int r_o = r_e + 8;

    w1_s[tid] = W1[tid];
    if (tid < 2) b1_s[tid] = b1[tid];

    float acc[16][4];
#pragma unroll
    for (int t = 0; t < 16; t++) {
        int col = 8 * t + 2 * tg;
        float2 bb = *(const float2*)(b0 + col);
        acc[t][0] = bb.x; acc[t][1] = bb.y;
        acc[t][2] = bb.x; acc[t][3] = bb.y;
    }
    for (int c = 0; c < 4; c++) {
        __syncthreads();
        fillA(AhU, AlU, nsrc, row0, c * 32, tid);
        fillB_g(BhU, BlU, g_BdecH, g_BdecL, c * 32, tid);
        __syncthreads();
        mma_chunk<BST>(AhU, AlU, BhU, BlU, acc, rw0, gid, tg);
    }

    // relu -> fp32 smem
#pragma unroll
    for (int t = 0; t < 16; t++) {
        int col = 8 * t + 2 * tg;
        *(float2*)(Hout + (rw0 + gid)     * 132 + col) =
            make_float2(fmaxf(acc[t][0], 0.f), fmaxf(acc[t][1], 0.f));
        *(float2*)(Hout + (rw0 + gid + 8) * 132 + col) =
            make_float2(fmaxf(acc[t][2], 0.f), fmaxf(acc[t][3], 0.f));
    }
    __syncthreads();

    // tail: 128 rows x 2 outputs, one thread each
    {
        int row = tid >> 1, c = tid & 1;
        float s = b1_s[c];
#pragma unroll 8
        for (int k = 0; k < 128; k++)
            s = fmaf(Hout[row * 132 + k], w1_s[k * 2 + c], s);
        int gr = row0 + row;
        if (gr < NN) out[gr * 2 + c] = s;
    }
}

// ---------------------------------------------------------------------------
extern "C" void kernel_launch(void* const* d_in, const int* in_sizes, int n_in,
                              void* d_out, int out_size) {
    const float* nodes   = (const float*)d_in[0];
    const float* edges   = (const float*)d_in[1];
    const int*   senders = (const int*)  d_in[2];
    const int*   recvs   = (const int*)  d_in[3];
    const float* enW0 = (const float*)d_in[4];
    const float* enb0 = (const float*)d_in[5];
    const float* enW1 = (const float*)d_in[6];
    const float* enb1 = (const float*)d_in[7];
    const float* eeW0 = (const float*)d_in[8];
    const float* eeb0 = (const float*)d_in[9];
    const float* eeW1 = (const float*)d_in[10];
    const float* eeb1 = (const float*)d_in[11];
    const float* Wmsg = (const float*)d_in[12];
    const float* nW0  = (const float*)d_in[13];
    const float* nb0  = (const float*)d_in[14];
    const float* nW1  = (const float*)d_in[15];
    const float* nb1  = (const float*)d_in[16];
    const float* Wnode= (const float*)d_in[17];
    const float* lng  = (const float*)d_in[18];
    const float* lnb  = (const float*)d_in[19];
    const float* dW0  = (const float*)d_in[20];
    const float* db0  = (const float*)d_in[21];
    const float* dW1  = (const float*)d_in[22];
    const float* db1  = (const float*)d_in[23];
    float* out = (float*)d_out;

    cudaFuncSetAttribute(k_enc_all_mma,  cudaFuncAttributeMaxDynamicSharedMemorySize, SM_ENC2);
    cudaFuncSetAttribute(k_cagg_mma,     cudaFuncAttributeMaxDynamicSharedMemorySize, SM_CAG);
    cudaFuncSetAttribute(k_node_upd_mma, cudaFuncAttributeMaxDynamicSharedMemorySize, SM_MMA);
    cudaFuncSetAttribute(k_dec_mma,      cudaFuncAttributeMaxDynamicSharedMemorySize, SM_DECM);

    // Setup: prep (fold1 + splits + zero), fold2, CSR build
    k_prep<<<PREP_Z, 256>>>(eeW1, eeb1, Wmsg, nW0, Wnode, nW1, enW1, dW0, eeW0, enW0);
    k_fold2<<<257, 128>>>(nW0, Wmsg);
    k_hist<<<(NEDGE + 255) / 256, 256>>>(recvs);
    k_scan<<<1, 1024>>>();
    k_fillcsr<<<(NEDGE + 255) / 256, 256>>>(senders, recvs);
    k_enc_all_mma<<<NT128 + ET128, 256, SM_ENC2>>>(nodes, enb0, enb1, edges, eeb0, recvs);
    k_cagg_mma<<<NT128, 256, SM_CAG>>>();

    for (int p = 0; p < NPASS; p++)
        k_node_upd_mma<<<NT128, 256, SM_MMA>>>(nb0, nb1, lng, lnb, p & 1);

    k_dec_mma<<<NT128, 256, SM_DECM>>>(db0, dW1, db1, out, NPASS & 1);
}

// round 17
// speedup vs baseline: 1.0981x; 1.0829x over previous
#include <cuda_runtime.h>
#include <cuda_bf16.h>
#include <math.h>

#define NN     50000
#define NEDGE  600000
#define HDIM   128
#define NPASS  5
#define LN_EPS 1e-6f

#define NT128      ((NN + 127) / 128)    // 391  (mma tiles, nodes)
#define ET128      ((NEDGE + 127) / 128) // 4688 (mma tiles, edges)
#define SCB        ((NN + 255) / 256)    // 196  (scan blocks)

typedef unsigned int uint32;
typedef unsigned short ushort16;

// Persistent device scratch — double-buffered node features
__device__ float g_n0[NN * HDIM];
__device__ float g_n1[NN * HDIM];
__device__ float g_hsum[NN * HDIM];
__device__ float g_cagg[NN * HDIM];
__device__ float g_T1[HDIM * HDIM];     // W1e @ Wm_bot
__device__ float g_tvec[HDIM];          // b1e @ Wm_bot
__device__ float g_bg[HDIM];

// Receiver-CSR of the edge list (built once per launch)
__device__ int g_rowptr[NN + 1];
__device__ int g_cursor[NN];
__device__ int g_col[NEDGE];
__device__ int g_bsum[256];             // block sums for hierarchical scan

// Split-bf16 weight tables, [N][K] k-contiguous (transposed)
__device__ __align__(16) ushort16 g_BtopH[HDIM * HDIM], g_BtopL[HDIM * HDIM]; // W0_top
__device__ __align__(16) ushort16 g_BWfH [HDIM * HDIM], g_BWfL [HDIM * HDIM]; // Wm_top@W0_bot
__device__ __align__(16) ushort16 g_BresH[HDIM * HDIM], g_BresL[HDIM * HDIM]; // Wn
__device__ __align__(16) ushort16 g_BoutH[HDIM * HDIM], g_BoutL[HDIM * HDIM]; // W1
__device__ __align__(16) ushort16 g_Ben1H[HDIM * HDIM], g_Ben1L[HDIM * HDIM]; // enc W1
__device__ __align__(16) ushort16 g_BWgH[HDIM * HDIM],  g_BWgL[HDIM * HDIM];  // (W1e@Wm_bot)@W0_bot
__device__ __align__(16) ushort16 g_BdecH[HDIM * HDIM], g_BdecL[HDIM * HDIM]; // dec W0
__device__ __align__(16) ushort16 g_BeH[HDIM * 16],   g_BeL[HDIM * 16];       // edge W0 [n][16k]
__device__ __align__(16) ushort16 g_Ben0H[HDIM * 32], g_Ben0L[HDIM * 32];     // enc W0 [n][32k]

// ---------------------------------------------------------------------------
// bf16 helpers + MMA
// ---------------------------------------------------------------------------
__device__ __forceinline__ uint32 pack_bf2(float x, float y) {
    __nv_bfloat162 t = __floats2bfloat162_rn(x, y);
    return *reinterpret_cast<uint32*>(&t);
}
__device__ __forceinline__ void split_bf(float v, ushort16& h, ushort16& l) {
    __nv_bfloat16 hb = __float2bfloat16_rn(v);
    float lo = v - __bfloat162float(hb);
    __nv_bfloat16 lb = __float2bfloat16_rn(lo);
    h = *reinterpret_cast<ushort16*>(&hb);
    l = *reinterpret_cast<ushort16*>(&lb);
}
__device__ __forceinline__ void split_pack2(float2 v, uint32& h, uint32& l) {
    float ex = __bfloat162float(__float2bfloat16_rn(v.x));
    float ey = __bfloat162float(__float2bfloat16_rn(v.y));
    h = pack_bf2(v.x, v.y);
    l = pack_bf2(v.x - ex, v.y - ey);
}
#define MMA16816(d, a0,a1,a2,a3, b0,b1) \
    asm volatile("mma.sync.aligned.m16n8k16.row.col.f32.bf16.bf16.f32 " \
        "{%0,%1,%2,%3},{%4,%5,%6,%7},{%8,%9},{%0,%1,%2,%3};" \
        : "+f"((d)[0]), "+f"((d)[1]), "+f"((d)[2]), "+f"((d)[3]) \
        : "r"(a0), "r"(a1), "r"(a2), "r"(a3), "r"(b0), "r"(b1))

// ---------------------------------------------------------------------------
// k_prep: fold1 + 5x splitB + splitE + zero(hsum, cursor), blockIdx dispatch
// ---------------------------------------------------------------------------
#define PREP_F1   129
#define PREP_SB   (PREP_F1 + 320)
#define PREP_SE   (PREP_SB + 24)
#define PREP_Z    (PREP_SE + 6300)

__global__ void k_prep(const float* __restrict__ W1e, const float* __restrict__ b1e,
                       const float* __restrict__ Wm,
                       const float* __restrict__ W0n, const float* __restrict__ Wnode,
                       const float* __restrict__ W1n, const float* __restrict__ We1,
                       const float* __restrict__ Wd0,
                       const float* __restrict__ W0e,
                       const float* __restrict__ We0) {   // encoder node W0 [32][128]
    __shared__ float a[HDIM];
    int bid = blockIdx.x;
    int tid = threadIdx.x;

    if (bid < PREP_F1) {
        int j = tid & 127;
        a[j] = (bid < 128) ? W1e[bid * HDIM + j] : b1e[j];
        __syncthreads();
        if (tid < 128) {
            float s = 0.f;
#pragma unroll 8
            for (int l = 0; l < HDIM; l++)
                s = fmaf(a[l], Wm[(HDIM + l) * HDIM + j], s);
            if (bid < 128) g_T1[bid * HDIM + j] = s;
            else           g_tvec[j] = s;
        }
    } else if (bid < PREP_SB) {
        int b = bid - PREP_F1;
        int which = b >> 6;
        const float* W; ushort16* dH; ushort16* dL;
        if (which == 0)      { W = W0n;   dH = g_BtopH; dL = g_BtopL; }
        else if (which == 1) { W = Wnode; dH = g_BresH; dL = g_BresL; }
        else if (which == 2) { W = W1n;   dH = g_BoutH; dL = g_BoutL; }
        else if (which == 3) { W = We1;   dH = g_Ben1H; dL = g_Ben1L; }
        else                 { W = Wd0;   dH = g_BdecH; dL = g_BdecL; }
        int idx = (b & 63) * 256 + tid;
        int k = idx >> 7, n = idx & 127;
        ushort16 h, l;
        split_bf(W[k * HDIM + n], h, l);
        dH[n * HDIM + k] = h;
        dL[n * HDIM + k] = l;
    } else if (bid < PREP_SE) {
        int idx = (bid - PREP_SB) * 256 + tid;   // 2048 + 4096
        if (idx < 2048) {
            int n = idx & 127, k = idx >> 7;
            ushort16 h, l;
            split_bf(W0e[k * HDIM + n], h, l);
            g_BeH[n * 16 + k] = h;
            g_BeL[n * 16 + k] = l;
        } else if (idx < 6144) {
            int i = idx - 2048;
            int n = i & 127, k = i >> 7;
            ushort16 h, l;
            split_bf(We0[k * HDIM + n], h, l);
            g_Ben0H[n * 32 + k] = h;
            g_Ben0L[n * 32 + k] = l;
        }
    } else if (bid < PREP_Z) {
        int i = (bid - PREP_SE) * 256 + tid;
        if (i < NN * 32) ((float4*)g_hsum)[i] = make_float4(0.f, 0.f, 0.f, 0.f);
        else {
            int d = i - NN * 32;
            if (d < NN / 4) ((int4*)g_cursor)[d] = make_int4(0, 0, 0, 0);
        }
    }
}

// fold2: bid<128: Wg row bid (split); bid==128: bg; bid>=129: Wf row (split)
__global__ void k_fold2(const float* __restrict__ W0n, const float* __restrict__ Wm) {
    __shared__ float a[HDIM];
    int j = threadIdx.x;
    int bid = blockIdx.x;
    if (bid < 128)       a[j] = g_T1[bid * HDIM + j];
    else if (bid == 128) a[j] = g_tvec[j];
    else                 a[j] = Wm[(bid - 129) * HDIM + j];
    __syncthreads();
    float s = 0.f;
#pragma unroll 8
    for (int l = 0; l < HDIM; l++)
        s = fmaf(a[l], W0n[(HDIM + l) * HDIM + j], s);
    if (bid < 128) {
        ushort16 h, l2; split_bf(s, h, l2);
        g_BWgH[j * HDIM + bid] = h;
        g_BWgL[j * HDIM + bid] = l2;
    } else if (bid == 128) g_bg[j] = s;
    else {
        int k = bid - 129;
        ushort16 h, l2; split_bf(s, h, l2);
        g_BWfH[j * HDIM + k] = h;
        g_BWfL[j * HDIM + k] = l2;
    }
}

// ---------------------------------------------------------------------------
// CSR build — hierarchical scan (R16 lesson: single-block scan cost 70 us)
// ---------------------------------------------------------------------------
__global__ void k_hist(const int* __restrict__ recvs) {
    int e = blockIdx.x * 256 + threadIdx.x;
    if (e < NEDGE) atomicAdd(g_cursor + recvs[e], 1);
}

// block-scan of counts: local exclusive prefixes -> g_rowptr, totals -> g_bsum
__global__ void k_scan1() {
    __shared__ int warp_s[8];
    int i = blockIdx.x * 256 + threadIdx.x;
    int lane = threadIdx.x & 31, wid = threadIdx.x >> 5;
    int v = (i < NN) ? g_cursor[i] : 0;
    int x = v;
#pragma unroll
    for (int off = 1; off < 32; off <<= 1) {
        int y = __shfl_up_sync(0xffffffffu, x, off);
        if (lane >= off) x += y;
    }
    if (lane == 31) warp_s[wid] = x;
    __syncthreads();
    if (wid == 0) {
        int wv = (lane < 8) ? warp_s[lane] : 0;
#pragma unroll
        for (int off = 1; off < 8; off <<= 1) {
            int y = __shfl_up_sync(0xffffffffu, wv, off);
            if (lane >= off) wv += y;
        }
        if (lane < 8) warp_s[lane] = wv;
    }
    __syncthreads();
    int excl = x - v + ((wid > 0) ? warp_s[wid - 1] : 0);
    if (i < NN) g_rowptr[i] = excl;
    if (threadIdx.x == 255) g_bsum[blockIdx.x] = excl + v;
}

// exclusive scan of SCB block totals (single block)
__global__ void k_scan2() {
    __shared__ int warp_s[8];
    int t = threadIdx.x;
    int lane = t & 31, wid = t >> 5;
    int v = (t < SCB) ? g_bsum[t] : 0;
    int x = v;
#pragma unroll
    for (int off = 1; off < 32; off <<= 1) {
        int y = __shfl_up_sync(0xffffffffu, x, off);
        if (lane >= off) x += y;
    }
    if (lane == 31) warp_s[wid] = x;
    __syncthreads();
    if (wid == 0) {
        int wv = (lane < 8) ? warp_s[lane] : 0;
#pragma unroll
        for (int off = 1; off < 8; off <<= 1) {
            int y = __shfl_up_sync(0xffffffffu, wv, off);
            if (lane >= off) wv += y;
        }
        if (lane < 8) warp_s[lane] = wv;
    }
    __syncthreads();
    int excl = x - v + ((wid > 0) ? warp_s[wid - 1] : 0);
    if (t < SCB) g_bsum[t] = excl;
    if (t == SCB - 1) g_rowptr[NN] = excl + v;
}

// apply block offsets; materialize rowptr + cursor
__global__ void k_scan3() {
    int i = blockIdx.x * 256 + threadIdx.x;
    if (i < NN) {
        int r = g_rowptr[i] + g_bsum[blockIdx.x];
        g_rowptr[i] = r;
        g_cursor[i] = r;
    }
}

__global__ void k_fillcsr(const int* __restrict__ senders,
                          const int* __restrict__ recvs) {
    int e = blockIdx.x * 256 + threadIdx.x;
    if (e < NEDGE) {
        int pos = atomicAdd(g_cursor + recvs[e], 1);
        g_col[pos] = senders[e];
    }
}

// ===========================================================================
// Shared MMA building blocks
// ===========================================================================
#define BST 20

__device__ __forceinline__ void fillB_g(uint32* BhU, uint32* BlU,
                                        const ushort16* __restrict__ gH,
                                        const ushort16* __restrict__ gL,
                                        int koff, int tid) {
    const uint4* sH = (const uint4*)gH;
    const uint4* sL = (const uint4*)gL;
    int kq0 = koff >> 3;
#pragma unroll
    for (int i = 0; i < 2; i++) {
        int p = tid + i * 256;
        int n = p >> 2, kq = p & 3;
        *(uint4*)(BhU + n * BST + 4 * kq) = sH[n * 16 + kq0 + kq];
        *(uint4*)(BlU + n * BST + 4 * kq) = sL[n * 16 + kq0 + kq];
    }
}

__device__ __forceinline__ void fillA(uint32* AhU, uint32* AlU,
                                      const float* __restrict__ src,
                                      int row0, int koff, int tid) {
#pragma unroll
    for (int i = 0; i < 4; i++) {
        int p = tid + i * 256;
        int row = p >> 3, q = p & 7;
        int gr = row0 + row;
        float4 v = make_float4(0.f, 0.f, 0.f, 0.f);
        if (gr < NN) v = *(const float4*)(src + (long)gr * HDIM + koff + 4 * q);
        float ex = __bfloat162float(__float2bfloat16_rn(v.x));
        float ey = __bfloat162float(__float2bfloat16_rn(v.y));
        float ez = __bfloat162float(__float2bfloat16_rn(v.z));
        float ew = __bfloat162float(__float2bfloat16_rn(v.w));
        uint2 hh = make_uint2(pack_bf2(v.x, v.y), pack_bf2(v.z, v.w));
        uint2 ll = make_uint2(pack_bf2(v.x - ex, v.y - ey), pack_bf2(v.z - ez, v.w - ew));
        *(uint2*)(AhU + row * BST + 2 * q) = hh;
        *(uint2*)(AlU + row * BST + 2 * q) = ll;
    }
}

template<int AS>
__device__ __forceinline__ void mma_chunk(const uint32* AhU, const uint32* AlU,
                                          const uint32* BhU, const uint32* BlU,
                                          float acc[16][4], int rw0, int gid, int tg) {
#pragma unroll
    for (int kb2 = 0; kb2 <= 8; kb2 += 8) {
        int a0i = (rw0 + gid) * AS + kb2 + tg;
        int a1i = a0i + 8 * AS;
        uint32 ah0 = AhU[a0i],     ah1 = AhU[a1i];
        uint32 ah2 = AhU[a0i + 4], ah3 = AhU[a1i + 4];
        uint32 al0 = AlU[a0i],     al1 = AlU[a1i];
        uint32 al2 = AlU[a0i + 4], al3 = AlU[a1i + 4];
#pragma unroll
        for (int t = 0; t < 16; t++) {
            int bi = (8 * t + gid) * BST + kb2 + tg;
            uint32 bh0 = BhU[bi], bh1 = BhU[bi + 4];
            uint32 bl0 = BlU[bi], bl1 = BlU[bi + 4];
            MMA16816(acc[t], ah0, ah1, ah2, ah3, bh0, bh1);
            MMA16816(acc[t], ah0, ah1, ah2, ah3, bl0, bl1);
            MMA16816(acc[t], al0, al1, al2, al3, bh0, bh1);
        }
    }
}

// ===========================================================================
// Merged MMA encoder kernel: blocks [0, NT128) encode nodes; [NT128, +ET128)
// encode edges + scatter to g_hsum.
// ===========================================================================
#define E_BH 0
#define E_BL (E_BH + 128 * BST)
#define E_HH (E_BL + 128 * BST)
#define E_HL (E_HH + 128 * 68)
#define SM_ENC2 ((E_HL + 128 * 68) * 4)    // 90112 B

__global__ void __launch_bounds__(256, 2) k_enc_all_mma(
        const float* __restrict__ xn,
        const float* __restrict__ nb0, const float* __restrict__ nb1,
        const float* __restrict__ xe, const float* __restrict__ eb0,
        const int* __restrict__ recvs) {
    extern __shared__ uint32 smu[];

    const int tid = threadIdx.x;
    const int w = tid >> 5, lane = tid & 31;
    const int gid = lane >> 2, tg = lane & 3;
    const int rw0 = w * 16;

    if (blockIdx.x < NT128) {
        uint32* BhU = smu + E_BH;
        uint32* BlU = smu + E_BL;
        uint32* HhU = smu + E_HH;
        uint32* HlU = smu + E_HL;

        const int row0 = blockIdx.x * 128;
        const int r_e = row0 + rw0 + gid;
        const int r_o = r_e + 8;

#pragma unroll
        for (int i = 0; i < 2; i++) {
            int p = tid + i * 256;
            *(uint4*)(BhU + 4 * p) = ((const uint4*)g_Ben0H)[p];
            *(uint4*)(BlU + 4 * p) = ((const uint4*)g_Ben0L)[p];
        }

        float2 z = make_float2(0.f, 0.f);
        uint32 ah[2][4], al[2][4];
#pragma unroll
        for (int kb = 0; kb < 2; kb++) {
            float2 vE0 = (r_e < NN) ? *(const float2*)(xn + (long)r_e * 32 + kb * 16 + 2 * tg)     : z;
            float2 vO0 = (r_o < NN) ? *(const float2*)(xn + (long)r_o * 32 + kb * 16 + 2 * tg)     : z;
            float2 vE1 = (r_e < NN) ? *(const float2*)(xn + (long)r_e * 32 + kb * 16 + 8 + 2 * tg) : z;
            float2 vO1 = (r_o < NN) ? *(const float2*)(xn + (long)r_o * 32 + kb * 16 + 8 + 2 * tg) : z;
            split_pack2(vE0, ah[kb][0], al[kb][0]);
            split_pack2(vO0, ah[kb][1], al[kb][1]);
            split_pack2(vE1, ah[kb][2], al[kb][2]);
            split_pack2(vO1, ah[kb][3], al[kb][3]);
        }
        __syncthreads();

        float acc[16][4];
#pragma unroll
        for (int t = 0; t < 16; t++) {
            int col = 8 * t + 2 * tg;
            float2 bb = *(const float2*)(nb0 + col);
            acc[t][0] = bb.x; acc[t][1] = bb.y;
            acc[t][2] = bb.x; acc[t][3] = bb.y;
        }
#pragma unroll
        for (int kb = 0; kb < 2; kb++) {
#pragma unroll
            for (int t = 0; t < 16; t++) {
                int bi = (8 * t + gid) * 16 + kb * 8 + tg;
                uint32 bh0 = BhU[bi], bh1 = BhU[bi + 4];
                uint32 bl0 = BlU[bi], bl1 = BlU[bi + 4];
                MMA16816(acc[t], ah[kb][0], ah[kb][1], ah[kb][2], ah[kb][3], bh0, bh1);
                MMA16816(acc[t], ah[kb][0], ah[kb][1], ah[kb][2], ah[kb][3], bl0, bl1);
                MMA16816(acc[t], al[kb][0], al[kb][1], al[kb][2], al[kb][3], bh0, bh1);
            }
        }

#pragma unroll
        for (int t = 0; t < 16; t++) {
            float h0 = fmaxf(acc[t][0], 0.f), h1 = fmaxf(acc[t][1], 0.f);
            float h2 = fmaxf(acc[t][2], 0.f), h3 = fmaxf(acc[t][3], 0.f);
            int ie = (rw0 + gid) * 68 + 4 * t + tg;
            int io = ie + 8 * 68;
            uint32 hh, ll;
            split_pack2(make_float2(h0, h1), hh, ll);
            HhU[ie] = hh; HlU[ie] = ll;
            split_pack2(make_float2(h2, h3), hh, ll);
            HhU[io] = hh; HlU[io] = ll;
        }

#pragma unroll
        for (int t = 0; t < 16; t++) {
            int col = 8 * t + 2 * tg;
            float2 bb = *(const float2*)(nb1 + col);
            acc[t][0] = bb.x; acc[t][1] = bb.y;
            acc[t][2] = bb.x; acc[t][3] = bb.y;
        }
        for (int c = 0; c < 4; c++) {
            __syncthreads();
            fillB_g(BhU, BlU, g_Ben1H, g_Ben1L, c * 32, tid);
            __syncthreads();
            mma_chunk<68>(HhU + 16 * c, HlU + 16 * c, BhU, BlU, acc, rw0, gid, tg);
        }

#pragma unroll
        for (int t = 0; t < 16; t++) {
            int col = 8 * t + 2 * tg;
            if (r_e < NN)
                *(float2*)(g_n0 + (long)r_e * HDIM + col) = make_float2(acc[t][0], acc[t][1]);
            if (r_o < NN)
                *(float2*)(g_n0 + (long)r_o * HDIM + col) = make_float2(acc[t][2], acc[t][3]);
        }
    } else {
        uint32* BhU  = smu;
        uint32* BlU  = smu + 1024;
        float*  Hout = (float*)(smu + 2048);

        const int row0 = (blockIdx.x - NT128) * 128;
        const int eE = row0 + rw0 + gid;
        const int eO = eE + 8;

#pragma unroll
        for (int i = 0; i < 4; i++) {
            int p = tid + i * 256;
            BhU[p] = ((const uint32*)g_BeH)[p];
            BlU[p] = ((const uint32*)g_BeL)[p];
        }

        float2 z = make_float2(0.f, 0.f);
        float2 vE0 = (eE < NEDGE) ? *(const float2*)(xe + (long)eE * 16 + 2 * tg)     : z;
        float2 vE1 = (eE < NEDGE) ? *(const float2*)(xe + (long)eE * 16 + 8 + 2 * tg) : z;
        float2 vO0 = (eO < NEDGE) ? *(const float2*)(xe + (long)eO * 16 + 2 * tg)     : z;
        float2 vO1 = (eO < NEDGE) ? *(const float2*)(xe + (long)eO * 16 + 8 + 2 * tg) : z;
        uint32 ah0, al0, ah1, al1, ah2, al2, ah3, al3;
        split_pack2(vE0, ah0, al0);
        split_pack2(vO0, ah1, al1);
        split_pack2(vE1, ah2, al2);
        split_pack2(vO1, ah3, al3);
        __syncthreads();

        float acc[16][4];
#pragma unroll
        for (int t = 0; t < 16; t++) {
            int col = 8 * t + 2 * tg;
            float2 bb = *(const float2*)(eb0 + col);
            acc[t][0] = bb.x; acc[t][1] = bb.y;
            acc[t][2] = bb.x; acc[t][3] = bb.y;
        }
#pragma unroll
        for (int t = 0; t < 16; t++) {
            int bi = (8 * t + gid) * 8 + tg;
            uint32 bh0 = BhU[bi], bh1 = BhU[bi + 4];
            uint32 bl0 = BlU[bi], bl1 = BlU[bi + 4];
            MMA16816(acc[t], ah0, ah1, ah2, ah3, bh0, bh1);
            MMA16816(acc[t], ah0, ah1, ah2, ah3, bl0, bl1);
            MMA16816(acc[t], al0, al1, al2, al3, bh0, bh1);
        }

#pragma unroll
        for (int t = 0; t < 16; t++) {
            int col = 8 * t + 2 * tg;
            *(float2*)(Hout + (rw0 + gid)     * 132 + col) =
                make_float2(fmaxf(acc[t][0], 0.f), fmaxf(acc[t][1], 0.f));
            *(float2*)(Hout + (rw0 + gid + 8) * 132 + col) =
                make_float2(fmaxf(acc[t][2], 0.f), fmaxf(acc[t][3], 0.f));
        }
        __syncthreads();

        int j = lane * 4;
        for (int r = 0; r < 16; r++) {
            int e = row0 + rw0 + r;
            if (e < NEDGE) {
                int rv = __ldg(recvs + e);
                float4 v = *(const float4*)(Hout + (rw0 + r) * 132 + j);
                float* dst = g_hsum + (long)rv * HDIM + j;
                asm volatile("red.global.add.v4.f32 [%0], {%1, %2, %3, %4};"
                             :: "l"(dst), "f"(v.x), "f"(v.y), "f"(v.z), "f"(v.w) : "memory");
            }
        }
    }
}

// ===========================================================================
// MMA cagg: c_agg = g_hsum @ Wg + deg * bg
// ===========================================================================
#define SM_CAG (4 * 128 * BST * 4)     // 40960 B

__global__ void __launch_bounds__(256, 2) k_cagg_mma() {
    extern __shared__ uint32 smu[];
    uint32* AhU = smu;
    uint32* AlU = smu + 128 * BST;
    uint32* BhU = smu + 2 * 128 * BST;
    uint32* BlU = smu + 3 * 128 * BST;

    const int tid = threadIdx.x;
    const int w = tid >> 5, lane = tid & 31;
    const int gid = lane >> 2, tg = lane & 3;
    const int rw0 = w * 16;
    const int row0 = blockIdx.x * 128;
    const int r_e = row0 + rw0 + gid;
    const int r_o = r_e + 8;

    float acc[16][4];
    {
        float de = (r_e < NN) ? (float)(g_rowptr[r_e + 1] - g_rowptr[r_e]) : 0.f;
        float dd = (r_o < NN) ? (float)(g_rowptr[r_o + 1] - g_rowptr[r_o]) : 0.f;
#pragma unroll
        for (int t = 0; t < 16; t++) {
            int col = 8 * t + 2 * tg;
            float2 bb = *(const float2*)(g_bg + col);
            acc[t][0] = de * bb.x; acc[t][1] = de * bb.y;
            acc[t][2] = dd * bb.x; acc[t][3] = dd * bb.y;
        }
    }
    for (int c = 0; c < 4; c++) {
        __syncthreads();
        fillA(AhU, AlU, g_hsum, row0, c * 32, tid);
        fillB_g(BhU, BlU, g_BWgH, g_BWgL, c * 32, tid);
        __syncthreads();
        mma_chunk<BST>(AhU, AlU, BhU, BlU, acc, rw0, gid, tg);
    }
#pragma unroll
    for (int t = 0; t < 16; t++) {
        int col = 8 * t + 2 * tg;
        if (r_e < NN)
            *(float2*)(g_cagg + (long)r_e * HDIM + col) = make_float2(acc[t][0], acc[t][1]);
        if (r_o < NN)
            *(float2*)(g_cagg + (long)r_o * HDIM + col) = make_float2(acc[t][2], acc[t][3]);
    }
}

// ===========================================================================
// Fused MMA node update (CSR gather with row-paired MLP8)
// ===========================================================================
#define U_AH 0
#define U_AL (U_AH + 128 * BST)
#define U_BH (U_AL + 128 * BST)
#define U_BL (U_BH + 128 * BST)
#define U_HH (U_BL + 128 * BST)
#define U_HL (U_HH + 128 * 68)
#define U_END (U_HL + 128 * 68)
#define SM_MMA (U_END * 4)          // 110592 bytes

__global__ void __launch_bounds__(256, 2) k_node_upd_mma(
        const float* __restrict__ b0, const float* __restrict__ b1,
        const float* __restrict__ lng, const float* __restrict__ lnb,
        int par) {
    extern __shared__ uint32 smu[];
    uint32* AhU = smu + U_AH;
    uint32* AlU = smu + U_AL;
    uint32* BhU = smu + U_BH;
    uint32* BlU = smu + U_BL;
    uint32* HhU = smu + U_HH;
    uint32* HlU = smu + U_HL;

    const float* ncur = (par == 0) ? g_n0 : g_n1;
    float*       nnxt = (par == 0) ? g_n1 : g_n0;

    const int tid = threadIdx.x;
    const int w = tid >> 5, lane = tid & 31;
    const int gid = lane >> 2, tg = lane & 3;
    const int rw0 = w * 16;
    const int row0 = blockIdx.x * 128;
    const int r_e = row0 + rw0 + gid;
    const int r_o = r_e + 8;
    const int jj = lane * 4;

    // ---- CSR gather, row-paired (rr, rr+8) for MLP8 ----
    for (int rr = 0; rr < 8; rr++) {
        int rowA = rw0 + rr, rowB = rowA + 8;
        int grA = row0 + rowA, grB = row0 + rowB;
        float A0 = 0.f, A1 = 0.f, A2 = 0.f, A3 = 0.f;
        float B0 = 0.f, B1 = 0.f, B2 = 0.f, B3 = 0.f;
        int eA = 0, nA = 0, eB = 0, nB = 0;
        if (grA < NN) { eA = g_rowptr[grA]; nA = g_rowptr[grA + 1]; }
        if (grB < NN) { eB = g_rowptr[grB]; nB = g_rowptr[grB + 1]; }
        while (eA + 4 <= nA && eB + 4 <= nB) {
            int a0 = g_col[eA], a1 = g_col[eA+1], a2 = g_col[eA+2], a3 = g_col[eA+3];
            int b0i = g_col[eB], b1i = g_col[eB+1], b2i = g_col[eB+2], b3i = g_col[eB+3];
            float4 u0 = *(const float4*)(ncur + (long)a0 * HDIM + jj);
            float4 u1 = *(const float4*)(ncur + (long)a1 * HDIM + jj);
            float4 u2 = *(const float4*)(ncur + (long)a2 * HDIM + jj);
            float4 u3 = *(const float4*)(ncur + (long)a3 * HDIM + jj);
            float4 w0 = *(const float4*)(ncur + (long)b0i * HDIM + jj);
            float4 w1 = *(const float4*)(ncur + (long)b1i * HDIM + jj);
            float4 w2 = *(const float4*)(ncur + (long)b2i * HDIM + jj);
            float4 w3 = *(const float4*)(ncur + (long)b3i * HDIM + jj);
            A0 += u0.x + u1.x + u2.x + u3.x;
            A1 += u0.y + u1.y + u2.y + u3.y;
            A2 += u0.z + u1.z + u2.z + u3.z;
            A3 += u0.w + u1.w + u2.w + u3.w;
            B0 += w0.x + w1.x + w2.x + w3.x;
            B1 += w0.y + w1.y + w2.y + w3.y;
            B2 += w0.z + w1.z + w2.z + w3.z;
            B3 += w0.w + w1.w + w2.w + w3.w;
            eA += 4; eB += 4;
        }
        for (; eA + 4 <= nA; eA += 4) {
            int a0 = g_col[eA], a1 = g_col[eA+1], a2 = g_col[eA+2], a3 = g_col[eA+3];
            float4 u0 = *(const float4*)(ncur + (long)a0 * HDIM + jj);
            float4 u1 = *(const float4*)(ncur + (long)a1 * HDIM + jj);
            float4 u2 = *(const float4*)(ncur + (long)a2 * HDIM + jj);
            float4 u3 = *(const float4*)(ncur + (long)a3 * HDIM + jj);
            A0 += u0.x + u1.x + u2.x + u3.x;
            A1 += u0.y + u1.y + u2.y + u3.y;
            A2 += u0.z + u1.z + u2.z + u3.z;
            A3 += u0.w + u1.w + u2.w + u3.w;
        }
        for (; eA < nA; eA++) {
            int s = g_col[eA];
            float4 v = *(const float4*)(ncur + (long)s * HDIM + jj);
            A0 += v.x; A1 += v.y; A2 += v.z; A3 += v.w;
        }
        for (; eB + 4 <= nB; eB += 4) {
            int b0i = g_col[eB], b1i = g_col[eB+1], b2i = g_col[eB+2], b3i = g_col[eB+3];
            float4 w0 = *(const float4*)(ncur + (long)b0i * HDIM + jj);
            float4 w1 = *(const float4*)(ncur + (long)b1i * HDIM + jj);
            float4 w2 = *(const float4*)(ncur + (long)b2i * HDIM + jj);
            float4 w3 = *(const float4*)(ncur + (long)b3i * HDIM + jj);
            B0 += w0.x + w1.x + w2.x + w3.x;
            B1 += w0.y + w1.y + w2.y + w3.y;
            B2 += w0.z + w1.z + w2.z + w3.z;
            B3 += w0.w + w1.w + w2.w + w3.w;
        }
        for (; eB < nB; eB++) {
            int s = g_col[eB];
            float4 v = *(const float4*)(ncur + (long)s * HDIM + jj);
            B0 += v.x; B1 += v.y; B2 += v.z; B3 += v.w;
        }
        uint32 h0, l0, h1, l1;
        split_pack2(make_float2(A0, A1), h0, l0);
        split_pack2(make_float2(A2, A3), h1, l1);
        *(uint2*)(HhU + rowA * 68 + lane * 2) = make_uint2(h0, h1);
        *(uint2*)(HlU + rowA * 68 + lane * 2) = make_uint2(l0, l1);
        split_pack2(make_float2(B0, B1), h0, l0);
        split_pack2(make_float2(B2, B3), h1, l1);
        *(uint2*)(HhU + rowB * 68 + lane * 2) = make_uint2(h0, h1);
        *(uint2*)(HlU + rowB * 68 + lane * 2) = make_uint2(l0, l1);
    }

    float acc[16][4];

    // ---- hidden accumulator init: b0 + c_agg ----
#pragma unroll
    for (int t = 0; t < 16; t++) {
        int col = 8 * t + 2 * tg;
        float2 bb = *(const float2*)(b0 + col);
        float2 ce = (r_e < NN) ? *(const float2*)(g_cagg + (long)r_e * HDIM + col)
                               : make_float2(0.f, 0.f);
        float2 co = (r_o < NN) ? *(const float2*)(g_cagg + (long)r_o * HDIM + col)
                               : make_float2(0.f, 0.f);
        acc[t][0] = bb.x + ce.x; acc[t][1] = bb.y + ce.y;
        acc[t][2] = bb.x + co.x; acc[t][3] = bb.y + co.y;
    }

    // ---- hidden: K = 256 — n chunks from gmem, S chunks from H ----
    for (int c = 0; c < 8; c++) {
        int koff = (c & 3) * 32;
        __syncthreads();
        if (c < 4) fillA(AhU, AlU, ncur, row0, koff, tid);
        fillB_g(BhU, BlU, (c < 4) ? g_BtopH : g_BWfH,
                          (c < 4) ? g_BtopL : g_BWfL, koff, tid);
        __syncthreads();
        if (c < 4) mma_chunk<BST>(AhU, AlU, BhU, BlU, acc, rw0, gid, tg);
        else       mma_chunk<68>(HhU + 16 * (c - 4), HlU + 16 * (c - 4),
                                 BhU, BlU, acc, rw0, gid, tg);
    }

    // ---- relu + split-store h to smem H ----
    __syncthreads();
#pragma unroll
    for (int t = 0; t < 16; t++) {
        float h0 = fmaxf(acc[t][0], 0.f), h1 = fmaxf(acc[t][1], 0.f);
        float h2 = fmaxf(acc[t][2], 0.f), h3 = fmaxf(acc[t][3], 0.f);
        int ie = (rw0 + gid) * 68 + 4 * t + tg;
        int io = ie + 8 * 68;
        uint32 hh, ll;
        split_pack2(make_float2(h0, h1), hh, ll);
        HhU[ie] = hh; HlU[ie] = ll;
        split_pack2(make_float2(h2, h3), hh, ll);
        HhU[io] = hh; HlU[io] = ll;
    }

    // ---- residual: acc = n @ Wn ----
#pragma unroll
    for (int t = 0; t < 16; t++) {
        acc[t][0] = 0.f; acc[t][1] = 0.f; acc[t][2] = 0.f; acc[t][3] = 0.f;
    }
    for (int c = 0; c < 4; c++) {
        __syncthreads();
        fillA(AhU, AlU, ncur, row0, c * 32, tid);
        fillB_g(BhU, BlU, g_BresH, g_BresL, c * 32, tid);
        __syncthreads();
        mma_chunk<BST>(AhU, AlU, BhU, BlU, acc, rw0, gid, tg);
    }

    // ---- output: acc += h @ W1 ----
    for (int c = 0; c < 4; c++) {
        __syncthreads();
        fillB_g(BhU, BlU, g_BoutH, g_BoutL, c * 32, tid);
        __syncthreads();
        mma_chunk<68>(HhU + 16 * c, HlU + 16 * c, BhU, BlU, acc, rw0, gid, tg);
    }

    // ---- + b1, LayerNorm, write other buffer ----
    float s1e = 0.f, s2e = 0.f, s1o = 0.f, s2o = 0.f;
#pragma unroll
    for (int t = 0; t < 16; t++) {
        int col = 8 * t + 2 * tg;
        float2 bb = *(const float2*)(b1 + col);
        acc[t][0] += bb.x; acc[t][1] += bb.y;
        acc[t][2] += bb.x; acc[t][3] += bb.y;
        s1e += acc[t][0] + acc[t][1];
        s2e += acc[t][0] * acc[t][0] + acc[t][1] * acc[t][1];
        s1o += acc[t][2] + acc[t][3];
        s2o += acc[t][2] * acc[t][2] + acc[t][3] * acc[t][3];
    }
#pragma unroll
    for (int off = 1; off <= 2; off <<= 1) {
        s1e += __shfl_xor_sync(0xffffffffu, s1e, off);
        s2e += __shfl_xor_sync(0xffffffffu, s2e, off);
        s1o += __shfl_xor_sync(0xffffffffu, s1o, off);
        s2o += __shfl_xor_sync(0xffffffffu, s2o, off);
    }
    float mu_e = s1e * (1.f / 128.f);
    float mu_o = s1o * (1.f / 128.f);
    float inv_e = rsqrtf(s2e * (1.f / 128.f) - mu_e * mu_e + LN_EPS);
    float inv_o = rsqrtf(s2o * (1.f / 128.f) - mu_o * mu_o + LN_EPS);

#pragma unroll
    for (int t = 0; t < 16; t++) {
        int col = 8 * t + 2 * tg;
        float2 gv = *(const float2*)(lng + col);
        float2 bv = *(const float2*)(lnb + col);
        if (r_e < NN) {
            float2 o;
            o.x = (acc[t][0] - mu_e) * inv_e * gv.x + bv.x;
            o.y = (acc[t][1] - mu_e) * inv_e * gv.y + bv.y;
            *(float2*)(nnxt + (long)r_e * HDIM + col) = o;
        }
        if (r_o < NN) {
            float2 o;
            o.x = (acc[t][2] - mu_o) * inv_o * gv.x + bv.x;
            o.y = (acc[t][3] - mu_o) * inv_o * gv.y + bv.y;
            *(float2*)(nnxt + (long)r_o * HDIM + col) = o;
        }
    }
}

// ===========================================================================
// MMA decoder: out = relu(n @ W0 + b0) @ W1 + b1    out: [NN,2]
// ===========================================================================
#define D_AH 0
#define D_AL (D_AH + 128 * BST)
#define D_BH (D_AL + 128 * BST)
#define D_BL (D_BH + 128 * BST)
#define D_HO (D_BL + 128 * BST)                 // fp32 h, [128][132]
#define D_W1 (D_HO + 128 * 132)                 // 256 floats
#define D_B1 (D_W1 + 256)                       // 2 floats
#define SM_DECM ((D_B1 + 2) * 4)                // 109576 B

__global__ void __launch_bounds__(256, 2) k_dec_mma(
        const float* __restrict__ b0,
        const float* __restrict__ W1, const float* __restrict__ b1,
        float* __restrict__ out, int par) {
    extern __shared__ uint32 smu[];
    uint32* AhU = smu + D_AH;
    uint32* AlU = smu + D_AL;
    uint32* BhU = smu + D_BH;
    uint32* BlU = smu + D_BL;
    float*  Hout = (float*)(smu + D_HO);
    float*  w1_s = (float*)(smu + D_W1);
    float*  b1_s = (float*)(smu + D_B1);

    const float* nsrc = (par == 0) ? g_n0 : g_n1;

    const int tid = threadIdx.x;
    const int w = tid >> 5, lane = tid & 31;
    const int gid = lane >> 2, tg = lane & 3;
    const int rw0 = w * 16;
    const int row0 = blockIdx.x * 128;
    const int r_e = row0 + rw0 + gid;
    const int r_o = r_e + 8;

    w1_s[tid] = W1[tid];
    if (tid < 2) b1_s[tid] = b1[tid];

    float acc[16][4];
#pragma unroll
    for (int t = 0; t < 16; t++) {
        int col = 8 * t + 2 * tg;
        float2 bb = *(const float2*)(b0 + col);
        acc[t][0] = bb.x; acc[t][1] = bb.y;
        acc[t][2] = bb.x; acc[t][3] = bb.y;
    }
    for (int c = 0; c < 4; c++) {
        __syncthreads();
        fillA(AhU, AlU, nsrc, row0, c * 32, tid);
        fillB_g(BhU, BlU, g_BdecH, g_BdecL, c * 32, tid);
        __syncthreads();
        mma_chunk<BST>(AhU, AlU, BhU, BlU, acc, rw0, gid, tg);
    }

    // relu -> fp32 smem
#pragma unroll
    for (int t = 0; t < 16; t++) {
        int col = 8 * t + 2 * tg;
        *(float2*)(Hout + (rw0 + gid)     * 132 + col) =
            make_float2(fmaxf(acc[t][0], 0.f), fmaxf(acc[t][1], 0.f));
        *(float2*)(Hout + (rw0 + gid + 8) * 132 + col) =
            make_float2(fmaxf(acc[t][2], 0.f), fmaxf(acc[t][3], 0.f));
    }
    __syncthreads();

    // tail: 128 rows x 2 outputs, one thread each
    {
        int row = tid >> 1, c = tid & 1;
        float s = b1_s[c];
#pragma unroll 8
        for (int k = 0; k < 128; k++)
            s = fmaf(Hout[row * 132 + k], w1_s[k * 2 + c], s);
        int gr = row0 + row;
        if (gr < NN) out[gr * 2 + c] = s;
    }
}

// ---------------------------------------------------------------------------
extern "C" void kernel_launch(void* const* d_in, const int* in_sizes, int n_in,
                              void* d_out, int out_size) {
    const float* nodes   = (const float*)d_in[0];
    const float* edges   = (const float*)d_in[1];
    const int*   senders = (const int*)  d_in[2];
    const int*   recvs   = (const int*)  d_in[3];
    const float* enW0 = (const float*)d_in[4];
    const float* enb0 = (const float*)d_in[5];
    const float* enW1 = (const float*)d_in[6];
    const float* enb1 = (const float*)d_in[7];
    const float* eeW0 = (const float*)d_in[8];
    const float* eeb0 = (const float*)d_in[9];
    const float* eeW1 = (const float*)d_in[10];
    const float* eeb1 = (const float*)d_in[11];
    const float* Wmsg = (const float*)d_in[12];
    const float* nW0  = (const float*)d_in[13];
    const float* nb0  = (const float*)d_in[14];
    const float* nW1  = (const float*)d_in[15];
    const float* nb1  = (const float*)d_in[16];
    const float* Wnode= (const float*)d_in[17];
    const float* lng  = (const float*)d_in[18];
    const float* lnb  = (const float*)d_in[19];
    const float* dW0  = (const float*)d_in[20];
    const float* db0  = (const float*)d_in[21];
    const float* dW1  = (const float*)d_in[22];
    const float* db1  = (const float*)d_in[23];
    float* out = (float*)d_out;

    cudaFuncSetAttribute(k_enc_all_mma,  cudaFuncAttributeMaxDynamicSharedMemorySize, SM_ENC2);
    cudaFuncSetAttribute(k_cagg_mma,     cudaFuncAttributeMaxDynamicSharedMemorySize, SM_CAG);
    cudaFuncSetAttribute(k_node_upd_mma, cudaFuncAttributeMaxDynamicSharedMemorySize, SM_MMA);
    cudaFuncSetAttribute(k_dec_mma,      cudaFuncAttributeMaxDynamicSharedMemorySize, SM_DECM);

    // Setup: prep (fold1 + splits + zero), fold2, CSR build (hierarchical scan)
    k_prep<<<PREP_Z, 256>>>(eeW1, eeb1, Wmsg, nW0, Wnode, nW1, enW1, dW0, eeW0, enW0);
    k_fold2<<<257, 128>>>(nW0, Wmsg);
    k_hist<<<(NEDGE + 255) / 256, 256>>>(recvs);
    k_scan1<<<SCB, 256>>>();
    k_scan2<<<1, 256>>>();
    k_scan3<<<SCB, 256>>>();
    k_fillcsr<<<(NEDGE + 255) / 256, 256>>>(senders, recvs);
    k_enc_all_mma<<<NT128 + ET128, 256, SM_ENC2>>>(nodes, enb0, enb1, edges, eeb0, recvs);
    k_cagg_mma<<<NT128, 256, SM_CAG>>>();

    for (int p = 0; p < NPASS; p++)
        k_node_upd_mma<<<NT128, 256, SM_MMA>>>(nb0, nb1, lng, lnb, p & 1);

    k_dec_mma<<<NT128, 256, SM_DECM>>>(db0, dW1, db1, out, NPASS & 1);
}